// round 10
// baseline (speedup 1.0000x reference)
#include <cuda_runtime.h>
#include <cuda_bf16.h>
#include <cstdint>
#include <math.h>

// Problem constants
#define BHC   16
#define NSEQ  4096
#define DDIM  64
#define MFEAT 256
#define EDIM  64
#define CHK   128
#define NCH   32

#define NORM_F   0.35355339059327373f
#define DIAG_C   0.0625f
#define RATIO_F  0.0625f
#define EPS_KF   1e-4f
#define EPS_DF   1e-6f

// Scratch (static device globals)
__device__ float    g_phi_q[BHC * NSEQ * MFEAT];   // 64 MiB (final phi_q)
__device__ float    g_phi_k[BHC * NSEQ * MFEAT];   // 64 MiB (E = exp(dd - diag))
__device__ float    g_S[BHC * NCH * MFEAT * EDIM]; // 32 MiB, per chunk [m 256][e 64]
__device__ float    g_z[BHC * NCH * MFEAT];
__device__ unsigned g_kmax[BHC];
__device__ float    g_proj_hi[MFEAT * DDIM];
__device__ float    g_proj_lo[MFEAT * DDIM];

// ---------------------------------------------------------------------------
__device__ __forceinline__ float tf32r(float x) {
    uint32_t u;
    asm("cvt.rna.tf32.f32 %0, %1;" : "=r"(u) : "f"(x));
    return __uint_as_float(u);
}
#define F2U(x) __float_as_uint(x)

__device__ __forceinline__ void mma8(float* c, uint32_t a0, uint32_t a1,
                                     uint32_t a2, uint32_t a3,
                                     uint32_t b0, uint32_t b1) {
    asm volatile("mma.sync.aligned.m16n8k8.row.col.f32.tf32.tf32.f32 "
                 "{%0,%1,%2,%3},{%4,%5,%6,%7},{%8,%9},{%0,%1,%2,%3};"
                 : "+f"(c[0]), "+f"(c[1]), "+f"(c[2]), "+f"(c[3])
                 : "r"(a0), "r"(a1), "r"(a2), "r"(a3), "r"(b0), "r"(b1));
}

__device__ __forceinline__ float decode_max(unsigned u) {
    return __uint_as_float((u & 0x80000000u) ? (u ^ 0x80000000u) : ~u);
}

// ---------------------------------------------------------------------------
__global__ void init_kmax_kernel() {
    if (threadIdx.x < BHC) g_kmax[threadIdx.x] = 0u;
}

__global__ void proj_prep_kernel(const float* __restrict__ proj) {
    int idx = blockIdx.x * blockDim.x + threadIdx.x;
    if (idx < MFEAT * DDIM) {
        float x = proj[idx] * NORM_F;
        float hi = tf32r(x);
        g_proj_hi[idx] = hi;
        g_proj_lo[idx] = tf32r(x - hi);
    }
}

// ---------------------------------------------------------------------------
// phi via split-tf32 mma, 512 threads / 16 warps.
// Warp (wg_m = wid>>3, wg_n = wid&7) covers rows [wg_m*64, +64) x j [wg_n*32, +32).
#define PH_QH 0
#define PH_QL (128 * 68)
#define PH_PH (2 * 128 * 68)
#define PH_PL (PH_PH + 256 * 68)
#define PH_PMAX (PH_PL + 256 * 68)            // [128][8]
#define PH_DSUM (PH_PMAX + 1024)              // [256]
#define PH_RMAX (PH_DSUM + 256)               // [128]
#define PHI_SMEMF (PH_RMAX + 128)

__global__ void __launch_bounds__(512, 1)
phi_mma_kernel(const float* __restrict__ data, int is_query) {
    extern __shared__ float sf[];
    float* qh   = sf + PH_QH;
    float* ql   = sf + PH_QL;
    float* ph   = sf + PH_PH;
    float* pl   = sf + PH_PL;
    float* pmax = sf + PH_PMAX;
    float* dsum = sf + PH_DSUM;
    float* rmax = sf + PH_RMAX;

    const int tid = threadIdx.x;
    const int wid = tid >> 5, lane = tid & 31;
    const int tq = lane >> 2, tr = lane & 3;
    const int wg_n = wid & 7, wg_m = wid >> 3;
    const size_t base = (size_t)blockIdx.x * 128;
    float* outg = is_query ? g_phi_q : g_phi_k;

    // stage q rows [128][64] -> hi/lo (stride 68)
    {
        const float4* src = reinterpret_cast<const float4*>(data + base * DDIM);
        #pragma unroll
        for (int i = 0; i < 4; ++i) {
            int idx = tid + i * 512;
            int r = idx >> 4, c4 = idx & 15;
            float4 t = src[idx];
            float4 h, l;
            h.x = tf32r(t.x); l.x = tf32r(t.x - h.x);
            h.y = tf32r(t.y); l.y = tf32r(t.y - h.y);
            h.z = tf32r(t.z); l.z = tf32r(t.z - h.z);
            h.w = tf32r(t.w); l.w = tf32r(t.w - h.w);
            *reinterpret_cast<float4*>(qh + r * 68 + 4 * c4) = h;
            *reinterpret_cast<float4*>(ql + r * 68 + 4 * c4) = l;
        }
    }
    // stage proj hi/lo [256][64]
    {
        const float4* sh = reinterpret_cast<const float4*>(g_proj_hi);
        const float4* sl = reinterpret_cast<const float4*>(g_proj_lo);
        #pragma unroll
        for (int i = 0; i < 8; ++i) {
            int idx = tid + i * 512;
            int r = idx >> 4, c4 = idx & 15;
            *reinterpret_cast<float4*>(ph + r * 68 + 4 * c4) = sh[idx];
            *reinterpret_cast<float4*>(pl + r * 68 + 4 * c4) = sl[idx];
        }
    }
    __syncthreads();

    // diag partials
    if (tid < 256) {
        int r = tid >> 1, hf = tid & 1;
        float s = 0.f;
        #pragma unroll 8
        for (int c = 0; c < 32; ++c) {
            float x = qh[r * 68 + hf * 32 + c] + ql[r * 68 + hf * 32 + c];
            s = fmaf(x, x, s);
        }
        dsum[tid] = s;
    }

    float acc[4][4][4];
    #pragma unroll
    for (int mt = 0; mt < 4; ++mt)
        #pragma unroll
        for (int nt = 0; nt < 4; ++nt)
            #pragma unroll
            for (int i = 0; i < 4; ++i) acc[mt][nt][i] = 0.f;

    const int nbase = wg_n * 32 + tq;
    #pragma unroll
    for (int ks = 0; ks < 8; ++ks) {
        const int k0 = ks * 8;
        uint32_t bh0[4], bh1[4], bl0[4], bl1[4];
        #pragma unroll
        for (int nt = 0; nt < 4; ++nt) {
            int n = nbase + nt * 8;
            bh0[nt] = F2U(ph[n * 68 + k0 + tr]);
            bh1[nt] = F2U(ph[n * 68 + k0 + tr + 4]);
            bl0[nt] = F2U(pl[n * 68 + k0 + tr]);
            bl1[nt] = F2U(pl[n * 68 + k0 + tr + 4]);
        }
        #pragma unroll
        for (int mt = 0; mt < 4; ++mt) {
            const int r0 = (wg_m * 4 + mt) * 16;
            uint32_t ah0 = F2U(qh[(r0 + tq) * 68 + k0 + tr]);
            uint32_t ah1 = F2U(qh[(r0 + tq + 8) * 68 + k0 + tr]);
            uint32_t ah2 = F2U(qh[(r0 + tq) * 68 + k0 + tr + 4]);
            uint32_t ah3 = F2U(qh[(r0 + tq + 8) * 68 + k0 + tr + 4]);
            uint32_t al0 = F2U(ql[(r0 + tq) * 68 + k0 + tr]);
            uint32_t al1 = F2U(ql[(r0 + tq + 8) * 68 + k0 + tr]);
            uint32_t al2 = F2U(ql[(r0 + tq) * 68 + k0 + tr + 4]);
            uint32_t al3 = F2U(ql[(r0 + tq + 8) * 68 + k0 + tr + 4]);
            #pragma unroll
            for (int nt = 0; nt < 4; ++nt) {
                mma8(acc[mt][nt], ah0, ah1, ah2, ah3, bh0[nt], bh1[nt]);
                mma8(acc[mt][nt], ah0, ah1, ah2, ah3, bl0[nt], bl1[nt]);
                mma8(acc[mt][nt], al0, al1, al2, al3, bh0[nt], bh1[nt]);
            }
        }
    }

    // per-warp row maxima of dd over this warp's 32-j slice
    #pragma unroll
    for (int mt = 0; mt < 4; ++mt) {
        const int rA = (wg_m * 4 + mt) * 16 + tq, rB = rA + 8;
        float mA = -3.4e38f, mB = -3.4e38f;
        #pragma unroll
        for (int nt = 0; nt < 4; ++nt) {
            mA = fmaxf(mA, fmaxf(acc[mt][nt][0], acc[mt][nt][1]));
            mB = fmaxf(mB, fmaxf(acc[mt][nt][2], acc[mt][nt][3]));
        }
        mA = fmaxf(mA, __shfl_xor_sync(0xffffffffu, mA, 1));
        mA = fmaxf(mA, __shfl_xor_sync(0xffffffffu, mA, 2));
        mB = fmaxf(mB, __shfl_xor_sync(0xffffffffu, mB, 1));
        mB = fmaxf(mB, __shfl_xor_sync(0xffffffffu, mB, 2));
        if (tr == 0) {
            pmax[rA * 8 + wg_n] = mA;
            pmax[rB * 8 + wg_n] = mB;
        }
    }
    __syncthreads();

    if (tid < 128) {
        float m = pmax[tid * 8];
        #pragma unroll
        for (int w = 1; w < 8; ++w) m = fmaxf(m, pmax[tid * 8 + w]);
        rmax[tid] = m;
    }
    __syncthreads();

    if (!is_query && tid == 0) {
        float bm = rmax[0];
        #pragma unroll 8
        for (int i = 1; i < 128; ++i) bm = fmaxf(bm, rmax[i]);
        unsigned u = __float_as_uint(bm);
        u = (u & 0x80000000u) ? ~u : (u | 0x80000000u);
        atomicMax(&g_kmax[blockIdx.x >> 5], u);
    }

    // exp + store
    #pragma unroll
    for (int mt = 0; mt < 4; ++mt) {
        const int rA = (wg_m * 4 + mt) * 16 + tq, rB = rA + 8;
        float offA = DIAG_C * (dsum[2 * rA] + dsum[2 * rA + 1]);
        float offB = DIAG_C * (dsum[2 * rB] + dsum[2 * rB + 1]);
        if (is_query) { offA += rmax[rA]; offB += rmax[rB]; }
        float* oA = outg + (base + rA) * MFEAT + wg_n * 32;
        float* oB = outg + (base + rB) * MFEAT + wg_n * 32;
        #pragma unroll
        for (int nt = 0; nt < 4; ++nt) {
            int c0 = nt * 8 + 2 * tr;
            float v0, v1, v2, v3;
            if (is_query) {
                v0 = RATIO_F * (__expf(acc[mt][nt][0] - offA) + EPS_KF);
                v1 = RATIO_F * (__expf(acc[mt][nt][1] - offA) + EPS_KF);
                v2 = RATIO_F * (__expf(acc[mt][nt][2] - offB) + EPS_KF);
                v3 = RATIO_F * (__expf(acc[mt][nt][3] - offB) + EPS_KF);
            } else {
                v0 = __expf(acc[mt][nt][0] - offA);
                v1 = __expf(acc[mt][nt][1] - offA);
                v2 = __expf(acc[mt][nt][2] - offB);
                v3 = __expf(acc[mt][nt][3] - offB);
            }
            *reinterpret_cast<float2*>(oA + c0) = make_float2(v0, v1);
            *reinterpret_cast<float2*>(oB + c0) = make_float2(v2, v3);
        }
    }
}

// ---------------------------------------------------------------------------
// chunk sums via mma, 512 threads / 16 warps (warp = 1 m-tile x 9 n-tiles)
#define CK_KS   0
#define CK_VS   (128 * 264)
#define CK_SMEMF (CK_VS + 128 * 72)
__global__ void __launch_bounds__(512, 1)
chunk_mma_kernel(const float* __restrict__ vin) {
    extern __shared__ float sf[];
    float* ksm = sf + CK_KS;
    float* vsm = sf + CK_VS;

    const int tid = threadIdx.x;
    const int wid = tid >> 5, lane = tid & 31;
    const int tq = lane >> 2, tr = lane & 3;
    const int cix = blockIdx.x;
    const size_t base_row = (size_t)(cix / NCH) * NSEQ + (size_t)(cix % NCH) * CHK;

    const float mx = decode_max(g_kmax[cix >> 5]);
    const float aK = RATIO_F * __expf(-mx);
    const float bK = RATIO_F * EPS_KF;

    // stage phi_k (affine) [128][256] -> [r][264]
    {
        const float4* src = reinterpret_cast<const float4*>(g_phi_k + base_row * MFEAT);
        #pragma unroll
        for (int i = 0; i < 16; ++i) {
            int idx = tid + i * 512;
            int r = idx >> 6, c4 = idx & 63;
            float4 t = src[idx];
            t.x = tf32r(fmaf(aK, t.x, bK)); t.y = tf32r(fmaf(aK, t.y, bK));
            t.z = tf32r(fmaf(aK, t.z, bK)); t.w = tf32r(fmaf(aK, t.w, bK));
            *reinterpret_cast<float4*>(ksm + r * 264 + 4 * c4) = t;
        }
    }
    // stage v [128][64] + ones column -> [r][72]
    {
        const float4* src = reinterpret_cast<const float4*>(vin + base_row * EDIM);
        #pragma unroll
        for (int i = 0; i < 4; ++i) {
            int idx = tid + i * 512;
            int r = idx >> 4, c4 = idx & 15;
            float4 t = src[idx];
            t.x = tf32r(t.x); t.y = tf32r(t.y); t.z = tf32r(t.z); t.w = tf32r(t.w);
            *reinterpret_cast<float4*>(vsm + r * 72 + 4 * c4) = t;
        }
        if (tid < 128) {
            *reinterpret_cast<float4*>(vsm + tid * 72 + 64) = make_float4(1.f, 0.f, 0.f, 0.f);
            *reinterpret_cast<float4*>(vsm + tid * 72 + 68) = make_float4(0.f, 0.f, 0.f, 0.f);
        }
    }
    __syncthreads();

    const int m0 = wid * 16;
    float acc[9][4];
    #pragma unroll
    for (int nt = 0; nt < 9; ++nt)
        #pragma unroll
        for (int i = 0; i < 4; ++i) acc[nt][i] = 0.f;

    #pragma unroll 4
    for (int ks = 0; ks < 16; ++ks) {
        const int k0 = ks * 8;
        uint32_t a0 = F2U(ksm[(k0 + tr) * 264 + m0 + tq]);
        uint32_t a1 = F2U(ksm[(k0 + tr) * 264 + m0 + tq + 8]);
        uint32_t a2 = F2U(ksm[(k0 + tr + 4) * 264 + m0 + tq]);
        uint32_t a3 = F2U(ksm[(k0 + tr + 4) * 264 + m0 + tq + 8]);
        #pragma unroll
        for (int nt = 0; nt < 9; ++nt) {
            uint32_t b0 = F2U(vsm[(k0 + tr) * 72 + nt * 8 + tq]);
            uint32_t b1 = F2U(vsm[(k0 + tr + 4) * 72 + nt * 8 + tq]);
            mma8(acc[nt], a0, a1, a2, a3, b0, b1);
        }
    }

    float* Sg = g_S + (size_t)cix * MFEAT * EDIM;
    float* zg = g_z + (size_t)cix * MFEAT;
    {
        int m = m0 + tq;
        #pragma unroll
        for (int nt = 0; nt < 8; ++nt) {
            int c0 = nt * 8 + 2 * tr;
            *reinterpret_cast<float2*>(Sg + m * EDIM + c0)
                = make_float2(acc[nt][0], acc[nt][1]);
            *reinterpret_cast<float2*>(Sg + (m + 8) * EDIM + c0)
                = make_float2(acc[nt][2], acc[nt][3]);
        }
        if (tr == 0) {
            zg[m]     = acc[8][0];
            zg[m + 8] = acc[8][2];
        }
    }
}

// ---------------------------------------------------------------------------
__global__ void prefix_kernel() {
    const int idx = blockIdx.x * blockDim.x + threadIdx.x;
    const int T1 = BHC * MFEAT * EDIM;
    if (idx < T1) {
        int bh = idx / (MFEAT * EDIM);
        int rem = idx % (MFEAT * EDIM);
        size_t base = (size_t)bh * NCH * MFEAT * EDIM + rem;
        float run = 0.f;
        #pragma unroll
        for (int c = 0; c < NCH; ++c) {
            size_t p = base + (size_t)c * MFEAT * EDIM;
            float t = g_S[p]; g_S[p] = run; run += t;
        }
    } else if (idx < T1 + BHC * MFEAT) {
        int j = idx - T1;
        int bh = j / MFEAT;
        int rem = j % MFEAT;
        size_t base = (size_t)bh * NCH * MFEAT + rem;
        float run = 0.f;
        #pragma unroll
        for (int c = 0; c < NCH; ++c) {
            size_t p = base + (size_t)c * MFEAT;
            float t = g_z[p]; g_z[p] = run; run += t;
        }
    }
}

// ---------------------------------------------------------------------------
// out kernel, 512 threads / 16 warps.
// Warp (wg_m = wid>>1, wg_h = wid&1): rows [wg_m*16, +16),
//   scores cols [wg_h*64, +64), inter/intra e-cols [wg_h*32, +32).
#define SA 140
#define SB 72
#define BUFA 0
#define BUFB (128 * SA)
#define BUFS (2 * 128 * SA)
#define ZSO  (BUFS + 128 * SB)
#define QZ4O (ZSO + 256)
#define SQ4O (QZ4O + 512)
#define SUMO (SQ4O + 512)
#define DENO (SUMO + 256)
#define OUT_SMEMF (DENO + 128)

__global__ void __launch_bounds__(512, 1)
out_mma_kernel(const float* __restrict__ vin, float* __restrict__ outp) {
    extern __shared__ float sf[];
    float* bufA = sf + BUFA;
    float* bufB = sf + BUFB;
    float* bufS = sf + BUFS;
    float* zs   = sf + ZSO;
    float* qz4  = sf + QZ4O;
    float* sq4  = sf + SQ4O;
    float* sums = sf + SUMO;
    float* den  = sf + DENO;

    const int tid = threadIdx.x;
    const int wid = tid >> 5, lane = tid & 31;
    const int tq = lane >> 2, tr = lane & 3;
    const int wg_m = wid >> 1, wg_h = wid & 1;
    const int cix = blockIdx.x;
    const size_t base_row = (size_t)(cix / NCH) * NSEQ + (size_t)(cix % NCH) * CHK;
    const int m0 = wg_m * 16;

    const float mx = decode_max(g_kmax[cix >> 5]);
    const float aK = RATIO_F * __expf(-mx);
    const float bK = RATIO_F * EPS_KF;

    if (tid < 256) zs[tid] = g_z[(size_t)cix * MFEAT + tid];

    float sacc[8][4];
    float iacc[4][4];
    #pragma unroll
    for (int nt = 0; nt < 8; ++nt)
        #pragma unroll
        for (int i = 0; i < 4; ++i) sacc[nt][i] = 0.f;
    #pragma unroll
    for (int nt = 0; nt < 4; ++nt)
        #pragma unroll
        for (int i = 0; i < 4; ++i) iacc[nt][i] = 0.f;

    float qzr = 0.f, sqr = 0.f;
    const float4* gq4 = reinterpret_cast<const float4*>(g_phi_q + base_row * MFEAT);
    const float4* gk4 = reinterpret_cast<const float4*>(g_phi_k + base_row * MFEAT);
    const int pr = tid >> 2, pquart = tid & 3;   // qz partial mapping

    for (int h = 0; h < 2; ++h) {
        __syncthreads();
        // stage phi_q / phi_k k-halves [128][128]
        #pragma unroll
        for (int i = 0; i < 8; ++i) {
            int idx = tid + i * 512;
            int r = idx >> 5, c4 = idx & 31;
            float4 tA = gq4[r * 64 + h * 32 + c4];
            float4 tB = gk4[r * 64 + h * 32 + c4];
            tA.x = tf32r(tA.x); tA.y = tf32r(tA.y); tA.z = tf32r(tA.z); tA.w = tf32r(tA.w);
            tB.x = tf32r(fmaf(aK, tB.x, bK)); tB.y = tf32r(fmaf(aK, tB.y, bK));
            tB.z = tf32r(fmaf(aK, tB.z, bK)); tB.w = tf32r(fmaf(aK, tB.w, bK));
            *reinterpret_cast<float4*>(bufA + r * SA + 4 * c4) = tA;
            *reinterpret_cast<float4*>(bufB + r * SA + 4 * c4) = tB;
        }
        // stage S half [128 m][64 e]
        {
            const float4* Sg4 = reinterpret_cast<const float4*>(
                g_S + (size_t)cix * MFEAT * EDIM + (size_t)h * 128 * EDIM);
            #pragma unroll
            for (int i = 0; i < 4; ++i) {
                int idx = tid + i * 512;
                int r = idx >> 4, c4 = idx & 15;
                float4 tS = Sg4[idx];
                tS.x = tf32r(tS.x); tS.y = tf32r(tS.y); tS.z = tf32r(tS.z); tS.w = tf32r(tS.w);
                *reinterpret_cast<float4*>(bufS + r * SB + 4 * c4) = tS;
            }
        }
        __syncthreads();

        #pragma unroll 2
        for (int ks = 0; ks < 16; ++ks) {
            const int k0 = ks * 8;
            uint32_t a0 = F2U(bufA[(m0 + tq) * SA + k0 + tr]);
            uint32_t a1 = F2U(bufA[(m0 + tq + 8) * SA + k0 + tr]);
            uint32_t a2 = F2U(bufA[(m0 + tq) * SA + k0 + tr + 4]);
            uint32_t a3 = F2U(bufA[(m0 + tq + 8) * SA + k0 + tr + 4]);
            #pragma unroll
            for (int nt = 0; nt < 8; ++nt) {
                int n = wg_h * 64 + nt * 8 + tq;
                uint32_t b0 = F2U(bufB[n * SA + k0 + tr]);
                uint32_t b1 = F2U(bufB[n * SA + k0 + tr + 4]);
                mma8(sacc[nt], a0, a1, a2, a3, b0, b1);
            }
            #pragma unroll
            for (int nt = 0; nt < 4; ++nt) {
                int c = wg_h * 32 + nt * 8 + tq;
                uint32_t b0 = F2U(bufS[(k0 + tr) * SB + c]);
                uint32_t b1 = F2U(bufS[(k0 + tr + 4) * SB + c]);
                mma8(iacc[nt], a0, a1, a2, a3, b0, b1);
            }
        }
        // qz/sq partials from staged phi_q half
        {
            const float* pq = bufA + pr * SA + pquart * 32;
            const float* pz = zs + h * 128 + pquart * 32;
            #pragma unroll 8
            for (int j = 0; j < 32; ++j) {
                qzr = fmaf(pq[j], pz[j], qzr);
                sqr += pq[j];
            }
        }
    }
    qz4[tid] = qzr; sq4[tid] = sqr;
    __syncthreads();

    // epilogue: masked scores -> bufA, partial rowsums -> sums[wg_h][128]
    const int rlo = m0 + tq, rhi = rlo + 8;
    {
        float rsl = 0.f, rsh = 0.f;
        #pragma unroll
        for (int nt = 0; nt < 8; ++nt) {
            int c0 = wg_h * 64 + nt * 8 + 2 * tr;
            float s0 = (c0     <= rlo) ? sacc[nt][0] : 0.f;
            float s1 = (c0 + 1 <= rlo) ? sacc[nt][1] : 0.f;
            float s2 = (c0     <= rhi) ? sacc[nt][2] : 0.f;
            float s3 = (c0 + 1 <= rhi) ? sacc[nt][3] : 0.f;
            rsl += s0 + s1; rsh += s2 + s3;
            *reinterpret_cast<float2*>(bufA + rlo * SA + c0) = make_float2(tf32r(s0), tf32r(s1));
            *reinterpret_cast<float2*>(bufA + rhi * SA + c0) = make_float2(tf32r(s2), tf32r(s3));
        }
        rsl += __shfl_xor_sync(0xffffffffu, rsl, 1);
        rsl += __shfl_xor_sync(0xffffffffu, rsl, 2);
        rsh += __shfl_xor_sync(0xffffffffu, rsh, 1);
        rsh += __shfl_xor_sync(0xffffffffu, rsh, 2);
        if (tr == 0) { sums[wg_h * 128 + rlo] = rsl; sums[wg_h * 128 + rhi] = rsh; }
    }
    // stage v -> bufB (stride SB)
    {
        const float4* vg4 = reinterpret_cast<const float4*>(vin + base_row * EDIM);
        #pragma unroll
        for (int i = 0; i < 4; ++i) {
            int idx = tid + i * 512;
            int r = idx >> 4, c4 = idx & 15;
            float4 t = vg4[idx];
            t.x = tf32r(t.x); t.y = tf32r(t.y); t.z = tf32r(t.z); t.w = tf32r(t.w);
            *reinterpret_cast<float4*>(bufB + r * SB + 4 * c4) = t;
        }
    }
    __syncthreads();

    if (tid < 128) {
        float d = qz4[4 * tid] + qz4[4 * tid + 1] + qz4[4 * tid + 2] + qz4[4 * tid + 3]
                + sums[tid] + sums[128 + tid]
                + EPS_DF * (sq4[4 * tid] + sq4[4 * tid + 1] + sq4[4 * tid + 2] + sq4[4 * tid + 3]);
        den[tid] = 1.f / d;
    }

    // intra: iacc += masked_scores @ v  (full K=128)
    #pragma unroll 2
    for (int ks = 0; ks < 16; ++ks) {
        const int k0 = ks * 8;
        uint32_t a0 = F2U(bufA[(m0 + tq) * SA + k0 + tr]);
        uint32_t a1 = F2U(bufA[(m0 + tq + 8) * SA + k0 + tr]);
        uint32_t a2 = F2U(bufA[(m0 + tq) * SA + k0 + tr + 4]);
        uint32_t a3 = F2U(bufA[(m0 + tq + 8) * SA + k0 + tr + 4]);
        #pragma unroll
        for (int nt = 0; nt < 4; ++nt) {
            int c = wg_h * 32 + nt * 8 + tq;
            uint32_t b0 = F2U(bufB[(k0 + tr) * SB + c]);
            uint32_t b1 = F2U(bufB[(k0 + tr + 4) * SB + c]);
            mma8(iacc[nt], a0, a1, a2, a3, b0, b1);
        }
    }
    __syncthreads();

    // final: out = iacc * inv_den   (cols wg_h*32 .. +32)
    {
        float il = den[rlo], ih = den[rhi];
        float* olo = outp + (base_row + rlo) * EDIM + wg_h * 32;
        float* ohi = outp + (base_row + rhi) * EDIM + wg_h * 32;
        #pragma unroll
        for (int nt = 0; nt < 4; ++nt) {
            int c0 = nt * 8 + 2 * tr;
            *reinterpret_cast<float2*>(olo + c0) = make_float2(iacc[nt][0] * il, iacc[nt][1] * il);
            *reinterpret_cast<float2*>(ohi + c0) = make_float2(iacc[nt][2] * ih, iacc[nt][3] * ih);
        }
    }
}

// ---------------------------------------------------------------------------
extern "C" void kernel_launch(void* const* d_in, const int* in_sizes, int n_in,
                              void* d_out, int out_size) {
    const float* big[3] = {nullptr, nullptr, nullptr};
    const float* proj = nullptr;
    int nb = 0;
    for (int i = 0; i < n_in; ++i) {
        if (in_sizes[i] == MFEAT * DDIM) proj = (const float*)d_in[i];
        else if (nb < 3) big[nb++] = (const float*)d_in[i];
    }
    const float* q = big[0];
    const float* k = big[1];
    const float* v = big[2];
    float* out = (float*)d_out;

    cudaFuncSetAttribute(phi_mma_kernel, cudaFuncAttributeMaxDynamicSharedMemorySize,
                         PHI_SMEMF * (int)sizeof(float));
    cudaFuncSetAttribute(chunk_mma_kernel, cudaFuncAttributeMaxDynamicSharedMemorySize,
                         CK_SMEMF * (int)sizeof(float));
    cudaFuncSetAttribute(out_mma_kernel, cudaFuncAttributeMaxDynamicSharedMemorySize,
                         OUT_SMEMF * (int)sizeof(float));

    init_kmax_kernel<<<1, 32>>>();
    proj_prep_kernel<<<64, 256>>>(proj);
    phi_mma_kernel<<<BHC * NSEQ / 128, 512, PHI_SMEMF * sizeof(float)>>>(q, 1);
    phi_mma_kernel<<<BHC * NSEQ / 128, 512, PHI_SMEMF * sizeof(float)>>>(k, 0);
    chunk_mma_kernel<<<BHC * NCH, 512, CK_SMEMF * sizeof(float)>>>(v);
    prefix_kernel<<<(BHC * MFEAT * EDIM + BHC * MFEAT) / 256, 256>>>();
    out_mma_kernel<<<BHC * NCH, 512, OUT_SMEMF * sizeof(float)>>>(v, out);
}

// round 12
// speedup vs baseline: 1.2594x; 1.2594x over previous
#include <cuda_runtime.h>
#include <cuda_bf16.h>
#include <cstdint>
#include <math.h>

// Problem constants
#define BHC   16
#define NSEQ  4096
#define DDIM  64
#define MFEAT 256
#define EDIM  64
#define CHK   128
#define NCH   32

#define NORM_F   0.35355339059327373f
#define DIAG_C   0.0625f
#define RATIO_F  0.0625f
#define EPS_KF   1e-4f
#define EPS_DF   1e-6f

// Scratch (static device globals)
__device__ float    g_phi_q[BHC * NSEQ * MFEAT];   // 64 MiB
__device__ float    g_phi_k[BHC * NSEQ * MFEAT];   // 64 MiB (E = exp(dd - diag))
__device__ float    g_S[BHC * NCH * MFEAT * EDIM]; // 32 MiB
__device__ float    g_z[BHC * NCH * MFEAT];
__device__ unsigned g_kmax[BHC];
__device__ uint32_t g_pjh[MFEAT * DDIM / 2];       // packed bf16-hi pairs
__device__ uint32_t g_pjl[MFEAT * DDIM / 2];       // packed bf16-lo pairs

// ---------------------------------------------------------------------------
__device__ __forceinline__ float tf32r(float x) {
    uint32_t u;
    asm("cvt.rna.tf32.f32 %0, %1;" : "=r"(u) : "f"(x));
    return __uint_as_float(u);
}
#define F2U(x) __float_as_uint(x)

__device__ __forceinline__ void mma8(float* c, uint32_t a0, uint32_t a1,
                                     uint32_t a2, uint32_t a3,
                                     uint32_t b0, uint32_t b1) {
    asm volatile("mma.sync.aligned.m16n8k8.row.col.f32.tf32.tf32.f32 "
                 "{%0,%1,%2,%3},{%4,%5,%6,%7},{%8,%9},{%0,%1,%2,%3};"
                 : "+f"(c[0]), "+f"(c[1]), "+f"(c[2]), "+f"(c[3])
                 : "r"(a0), "r"(a1), "r"(a2), "r"(a3), "r"(b0), "r"(b1));
}

__device__ __forceinline__ void mma16b(float* c, uint32_t a0, uint32_t a1,
                                       uint32_t a2, uint32_t a3,
                                       uint32_t b0, uint32_t b1) {
    asm volatile("mma.sync.aligned.m16n8k16.row.col.f32.bf16.bf16.f32 "
                 "{%0,%1,%2,%3},{%4,%5,%6,%7},{%8,%9},{%0,%1,%2,%3};"
                 : "+f"(c[0]), "+f"(c[1]), "+f"(c[2]), "+f"(c[3])
                 : "r"(a0), "r"(a1), "r"(a2), "r"(a3), "r"(b0), "r"(b1));
}

__device__ __forceinline__ float decode_max(unsigned u) {
    return __uint_as_float((u & 0x80000000u) ? (u ^ 0x80000000u) : ~u);
}

__device__ __forceinline__ void split_pack(float a, float b, uint32_t& hi, uint32_t& lo) {
    __nv_bfloat16 ha = __float2bfloat16_rn(a);
    __nv_bfloat16 hb = __float2bfloat16_rn(b);
    __nv_bfloat16 la = __float2bfloat16_rn(a - __bfloat162float(ha));
    __nv_bfloat16 lb = __float2bfloat16_rn(b - __bfloat162float(hb));
    __nv_bfloat162 hv = __halves2bfloat162(ha, hb);
    __nv_bfloat162 lv = __halves2bfloat162(la, lb);
    hi = *reinterpret_cast<uint32_t*>(&hv);
    lo = *reinterpret_cast<uint32_t*>(&lv);
}

// ---------------------------------------------------------------------------
__global__ void init_kmax_kernel() {
    if (threadIdx.x < BHC) g_kmax[threadIdx.x] = 0u;
}

// pre-split NORM*proj into packed bf16 hi/lo pairs
__global__ void proj_prep_kernel(const float* __restrict__ proj) {
    int idx = blockIdx.x * blockDim.x + threadIdx.x;   // pair index
    if (idx < MFEAT * DDIM / 2) {
        float a = proj[2 * idx] * NORM_F;
        float b = proj[2 * idx + 1] * NORM_F;
        uint32_t h, l;
        split_pack(a, b, h, l);
        g_pjh[idx] = h;
        g_pjl[idx] = l;
    }
}

// ---------------------------------------------------------------------------
// phi via split-bf16 mma (hi*hi + hi*lo + lo*hi; error ~2^-18), 512 threads.
// Warp (wg_m = wid>>3, wg_n = wid&7): rows [wg_m*64,+64) x j [wg_n*32,+32).
// smem words (uint32/float):
#define PH_QH  0
#define PH_QL  4608
#define PH_PHB 9216
#define PH_PLB 18432
#define PH_PMAX 27648           // [128][8]
#define PH_DSUM 28672           // [256]
#define PH_RMAX 28928           // [128]
#define PHI_SMEMW 29056

__global__ void __launch_bounds__(512, 1)
phi_mma_kernel(const float* __restrict__ data, int is_query) {
    extern __shared__ uint32_t su[];
    uint32_t* qhb = su + PH_QH;       // [128][36] packed bf16 pairs
    uint32_t* qlb = su + PH_QL;
    uint32_t* phb = su + PH_PHB;      // [256][36]
    uint32_t* plb = su + PH_PLB;
    float* pmax = reinterpret_cast<float*>(su + PH_PMAX);
    float* dsum = reinterpret_cast<float*>(su + PH_DSUM);
    float* rmax = reinterpret_cast<float*>(su + PH_RMAX);

    const int tid = threadIdx.x;
    const int wid = tid >> 5, lane = tid & 31;
    const int tq = lane >> 2, tr = lane & 3;
    const int wg_n = wid & 7, wg_m = wid >> 3;
    const size_t base = (size_t)blockIdx.x * 128;
    float* outg = is_query ? g_phi_q : g_phi_k;

    // stage q rows [128][64] -> split bf16 pairs [r][36]
    {
        const float4* src = reinterpret_cast<const float4*>(data + base * DDIM);
        #pragma unroll
        for (int i = 0; i < 4; ++i) {
            int idx = tid + i * 512;
            int r = idx >> 4, c4 = idx & 15;
            float4 t = src[idx];
            uint32_t h0, l0, h1, l1;
            split_pack(t.x, t.y, h0, l0);
            split_pack(t.z, t.w, h1, l1);
            *reinterpret_cast<uint2*>(qhb + r * 36 + 2 * c4) = make_uint2(h0, h1);
            *reinterpret_cast<uint2*>(qlb + r * 36 + 2 * c4) = make_uint2(l0, l1);
        }
    }
    // stage proj packed pairs [256][32] -> [r][36]
    {
        const uint4* sh = reinterpret_cast<const uint4*>(g_pjh);
        const uint4* sl = reinterpret_cast<const uint4*>(g_pjl);
        #pragma unroll
        for (int i = 0; i < 4; ++i) {
            int idx = tid + i * 512;                 // uint4 index (2048 total)
            int r = idx >> 3, k4 = idx & 7;
            *reinterpret_cast<uint4*>(phb + r * 36 + 4 * k4) = sh[idx];
            *reinterpret_cast<uint4*>(plb + r * 36 + 4 * k4) = sl[idx];
        }
    }
    __syncthreads();

    // diag partials from reconstructed q
    if (tid < 256) {
        int r = tid >> 1, hf = tid & 1;
        float s = 0.f;
        #pragma unroll 8
        for (int c = 0; c < 16; ++c) {
            uint32_t hu = qhb[r * 36 + hf * 16 + c];
            uint32_t lu = qlb[r * 36 + hf * 16 + c];
            float2 h = __bfloat1622float2(*reinterpret_cast<__nv_bfloat162*>(&hu));
            float2 l = __bfloat1622float2(*reinterpret_cast<__nv_bfloat162*>(&lu));
            float x0 = h.x + l.x, x1 = h.y + l.y;
            s = fmaf(x0, x0, fmaf(x1, x1, s));
        }
        dsum[tid] = s;
    }

    float acc[4][4][4];
    #pragma unroll
    for (int mt = 0; mt < 4; ++mt)
        #pragma unroll
        for (int nt = 0; nt < 4; ++nt)
            #pragma unroll
            for (int i = 0; i < 4; ++i) acc[mt][nt][i] = 0.f;

    const int nbase = wg_n * 32 + tq;
    #pragma unroll
    for (int ki = 0; ki < 4; ++ki) {               // 4 k-iters of K=16
        const int kp0 = ki * 8;                    // pair offset
        uint32_t bh0[4], bh1[4], bl0[4], bl1[4];
        #pragma unroll
        for (int nt = 0; nt < 4; ++nt) {
            int n = nbase + nt * 8;
            bh0[nt] = phb[n * 36 + kp0 + tr];
            bh1[nt] = phb[n * 36 + kp0 + tr + 4];
            bl0[nt] = plb[n * 36 + kp0 + tr];
            bl1[nt] = plb[n * 36 + kp0 + tr + 4];
        }
        #pragma unroll
        for (int mt = 0; mt < 4; ++mt) {
            const int r0 = (wg_m * 4 + mt) * 16;
            uint32_t ah0 = qhb[(r0 + tq) * 36 + kp0 + tr];
            uint32_t ah1 = qhb[(r0 + tq + 8) * 36 + kp0 + tr];
            uint32_t ah2 = qhb[(r0 + tq) * 36 + kp0 + tr + 4];
            uint32_t ah3 = qhb[(r0 + tq + 8) * 36 + kp0 + tr + 4];
            uint32_t al0 = qlb[(r0 + tq) * 36 + kp0 + tr];
            uint32_t al1 = qlb[(r0 + tq + 8) * 36 + kp0 + tr];
            uint32_t al2 = qlb[(r0 + tq) * 36 + kp0 + tr + 4];
            uint32_t al3 = qlb[(r0 + tq + 8) * 36 + kp0 + tr + 4];
            #pragma unroll
            for (int nt = 0; nt < 4; ++nt) {
                mma16b(acc[mt][nt], ah0, ah1, ah2, ah3, bh0[nt], bh1[nt]);
                mma16b(acc[mt][nt], ah0, ah1, ah2, ah3, bl0[nt], bl1[nt]);
                mma16b(acc[mt][nt], al0, al1, al2, al3, bh0[nt], bh1[nt]);
            }
        }
    }

    // per-warp row maxima over this warp's 32-j slice
    #pragma unroll
    for (int mt = 0; mt < 4; ++mt) {
        const int rA = (wg_m * 4 + mt) * 16 + tq, rB = rA + 8;
        float mA = -3.4e38f, mB = -3.4e38f;
        #pragma unroll
        for (int nt = 0; nt < 4; ++nt) {
            mA = fmaxf(mA, fmaxf(acc[mt][nt][0], acc[mt][nt][1]));
            mB = fmaxf(mB, fmaxf(acc[mt][nt][2], acc[mt][nt][3]));
        }
        mA = fmaxf(mA, __shfl_xor_sync(0xffffffffu, mA, 1));
        mA = fmaxf(mA, __shfl_xor_sync(0xffffffffu, mA, 2));
        mB = fmaxf(mB, __shfl_xor_sync(0xffffffffu, mB, 1));
        mB = fmaxf(mB, __shfl_xor_sync(0xffffffffu, mB, 2));
        if (tr == 0) {
            pmax[rA * 8 + wg_n] = mA;
            pmax[rB * 8 + wg_n] = mB;
        }
    }
    __syncthreads();

    if (tid < 128) {
        float m = pmax[tid * 8];
        #pragma unroll
        for (int w = 1; w < 8; ++w) m = fmaxf(m, pmax[tid * 8 + w]);
        rmax[tid] = m;
    }
    __syncthreads();

    if (!is_query && wid == 0) {
        float m = -3.4e38f;
        #pragma unroll
        for (int i = 0; i < 4; ++i) m = fmaxf(m, rmax[lane * 4 + i]);
        #pragma unroll
        for (int o = 16; o > 0; o >>= 1)
            m = fmaxf(m, __shfl_xor_sync(0xffffffffu, m, o));
        if (lane == 0) {
            unsigned u = __float_as_uint(m);
            u = (u & 0x80000000u) ? ~u : (u | 0x80000000u);
            atomicMax(&g_kmax[blockIdx.x >> 5], u);
        }
    }

    // exp + store
    #pragma unroll
    for (int mt = 0; mt < 4; ++mt) {
        const int rA = (wg_m * 4 + mt) * 16 + tq, rB = rA + 8;
        float offA = DIAG_C * (dsum[2 * rA] + dsum[2 * rA + 1]);
        float offB = DIAG_C * (dsum[2 * rB] + dsum[2 * rB + 1]);
        if (is_query) { offA += rmax[rA]; offB += rmax[rB]; }
        float* oA = outg + (base + rA) * MFEAT + wg_n * 32;
        float* oB = outg + (base + rB) * MFEAT + wg_n * 32;
        #pragma unroll
        for (int nt = 0; nt < 4; ++nt) {
            int c0 = nt * 8 + 2 * tr;
            float v0, v1, v2, v3;
            if (is_query) {
                v0 = RATIO_F * (__expf(acc[mt][nt][0] - offA) + EPS_KF);
                v1 = RATIO_F * (__expf(acc[mt][nt][1] - offA) + EPS_KF);
                v2 = RATIO_F * (__expf(acc[mt][nt][2] - offB) + EPS_KF);
                v3 = RATIO_F * (__expf(acc[mt][nt][3] - offB) + EPS_KF);
            } else {
                v0 = __expf(acc[mt][nt][0] - offA);
                v1 = __expf(acc[mt][nt][1] - offA);
                v2 = __expf(acc[mt][nt][2] - offB);
                v3 = __expf(acc[mt][nt][3] - offB);
            }
            *reinterpret_cast<float2*>(oA + c0) = make_float2(v0, v1);
            *reinterpret_cast<float2*>(oB + c0) = make_float2(v2, v3);
        }
    }
}

// ---------------------------------------------------------------------------
// chunk sums via mma (256 threads, R8 config): C[m,e(+z)] = phik^T @ [v|1]
#define CK_KS   0
#define CK_VS   (128 * 264)
#define CK_SMEMF (CK_VS + 128 * 72)
__global__ void __launch_bounds__(256, 1)
chunk_mma_kernel(const float* __restrict__ vin) {
    extern __shared__ float sf[];
    float* ksm = sf + CK_KS;
    float* vsm = sf + CK_VS;

    const int tid = threadIdx.x;
    const int wid = tid >> 5, lane = tid & 31;
    const int tq = lane >> 2, tr = lane & 3;
    const int qr = lane >> 3, qc = lane & 7;
    const int cix = blockIdx.x;
    const size_t base_row = (size_t)(cix / NCH) * NSEQ + (size_t)(cix % NCH) * CHK;

    const float mx = decode_max(g_kmax[cix >> 5]);
    const float aK = RATIO_F * __expf(-mx);
    const float bK = RATIO_F * EPS_KF;

    {
        const float4* src = reinterpret_cast<const float4*>(g_phi_k + base_row * MFEAT);
        #pragma unroll
        for (int j = 0; j < 4; ++j) {
            int r = wid * 4 + qr + 32 * j;
            #pragma unroll
            for (int i = 0; i < 8; ++i) {
                int c4 = qc + 8 * i;
                float4 t = src[r * 64 + c4];
                t.x = tf32r(fmaf(aK, t.x, bK)); t.y = tf32r(fmaf(aK, t.y, bK));
                t.z = tf32r(fmaf(aK, t.z, bK)); t.w = tf32r(fmaf(aK, t.w, bK));
                *reinterpret_cast<float4*>(ksm + r * 264 + 4 * c4) = t;
            }
        }
    }
    {
        const float4* src = reinterpret_cast<const float4*>(vin + base_row * EDIM);
        #pragma unroll
        for (int j = 0; j < 4; ++j) {
            int r = wid * 4 + qr + 32 * j;
            #pragma unroll
            for (int i = 0; i < 2; ++i) {
                int c4 = qc + 8 * i;
                float4 t = src[r * 16 + c4];
                t.x = tf32r(t.x); t.y = tf32r(t.y); t.z = tf32r(t.z); t.w = tf32r(t.w);
                *reinterpret_cast<float4*>(vsm + r * 72 + 4 * c4) = t;
            }
        }
        if (tid < 128) {
            *reinterpret_cast<float4*>(vsm + tid * 72 + 64) = make_float4(1.f, 0.f, 0.f, 0.f);
            *reinterpret_cast<float4*>(vsm + tid * 72 + 68) = make_float4(0.f, 0.f, 0.f, 0.f);
        }
    }
    __syncthreads();

    const int m0 = wid * 32;
    float acc[2][9][4];
    #pragma unroll
    for (int mt = 0; mt < 2; ++mt)
        #pragma unroll
        for (int nt = 0; nt < 9; ++nt)
            #pragma unroll
            for (int i = 0; i < 4; ++i) acc[mt][nt][i] = 0.f;

    #pragma unroll 4
    for (int ks = 0; ks < 16; ++ks) {
        const int k0 = ks * 8;
        uint32_t b0[9], b1[9];
        #pragma unroll
        for (int nt = 0; nt < 9; ++nt) {
            b0[nt] = F2U(vsm[(k0 + tr) * 72 + nt * 8 + tq]);
            b1[nt] = F2U(vsm[(k0 + tr + 4) * 72 + nt * 8 + tq]);
        }
        #pragma unroll
        for (int mt = 0; mt < 2; ++mt) {
            const int mb = m0 + mt * 16;
            uint32_t a0 = F2U(ksm[(k0 + tr) * 264 + mb + tq]);
            uint32_t a1 = F2U(ksm[(k0 + tr) * 264 + mb + tq + 8]);
            uint32_t a2 = F2U(ksm[(k0 + tr + 4) * 264 + mb + tq]);
            uint32_t a3 = F2U(ksm[(k0 + tr + 4) * 264 + mb + tq + 8]);
            #pragma unroll
            for (int nt = 0; nt < 9; ++nt)
                mma8(acc[mt][nt], a0, a1, a2, a3, b0[nt], b1[nt]);
        }
    }

    float* Sg = g_S + (size_t)cix * MFEAT * EDIM;
    float* zg = g_z + (size_t)cix * MFEAT;
    #pragma unroll
    for (int mt = 0; mt < 2; ++mt) {
        int m = m0 + mt * 16 + tq;
        #pragma unroll
        for (int nt = 0; nt < 8; ++nt) {
            int c0 = nt * 8 + 2 * tr;
            *reinterpret_cast<float2*>(Sg + m * EDIM + c0)
                = make_float2(acc[mt][nt][0], acc[mt][nt][1]);
            *reinterpret_cast<float2*>(Sg + (m + 8) * EDIM + c0)
                = make_float2(acc[mt][nt][2], acc[mt][nt][3]);
        }
        if (tr == 0) {
            zg[m]     = acc[mt][8][0];
            zg[m + 8] = acc[mt][8][2];
        }
    }
}

// ---------------------------------------------------------------------------
__global__ void prefix_kernel() {
    const int idx = blockIdx.x * blockDim.x + threadIdx.x;
    const int T1 = BHC * MFEAT * EDIM;
    if (idx < T1) {
        int bh = idx / (MFEAT * EDIM);
        int rem = idx % (MFEAT * EDIM);
        size_t base = (size_t)bh * NCH * MFEAT * EDIM + rem;
        float run = 0.f;
        #pragma unroll
        for (int c = 0; c < NCH; ++c) {
            size_t p = base + (size_t)c * MFEAT * EDIM;
            float t = g_S[p]; g_S[p] = run; run += t;
        }
    } else if (idx < T1 + BHC * MFEAT) {
        int j = idx - T1;
        int bh = j / MFEAT;
        int rem = j % MFEAT;
        size_t base = (size_t)bh * NCH * MFEAT + rem;
        float run = 0.f;
        #pragma unroll
        for (int c = 0; c < NCH; ++c) {
            size_t p = base + (size_t)c * MFEAT;
            float t = g_z[p]; g_z[p] = run; run += t;
        }
    }
}

// ---------------------------------------------------------------------------
// out kernel (256 threads, R8 config)
#define SA 140
#define SB 72
#define BUFA 0
#define BUFB (128 * SA)
#define BUFS (2 * 128 * SA)
#define ZSO  (BUFS + 128 * SB)
#define QZ2O (ZSO + 256)
#define SQ2O (QZ2O + 256)
#define SUMO (SQ2O + 256)
#define DENO (SUMO + 128)
#define OUT_SMEMF (DENO + 128)

__global__ void __launch_bounds__(256, 1)
out_mma_kernel(const float* __restrict__ vin, float* __restrict__ outp) {
    extern __shared__ float sf[];
    float* bufA = sf + BUFA;
    float* bufB = sf + BUFB;
    float* bufS = sf + BUFS;
    float* zs   = sf + ZSO;
    float* qz2  = sf + QZ2O;
    float* sq2  = sf + SQ2O;
    float* sums = sf + SUMO;
    float* den  = sf + DENO;

    const int tid = threadIdx.x;
    const int wid = tid >> 5, lane = tid & 31;
    const int tq = lane >> 2, tr = lane & 3;
    const int qr = lane >> 3, qc = lane & 7;
    const int cix = blockIdx.x;
    const size_t base_row = (size_t)(cix / NCH) * NSEQ + (size_t)(cix % NCH) * CHK;
    const int m0 = wid * 16;

    const float mx = decode_max(g_kmax[cix >> 5]);
    const float aK = RATIO_F * __expf(-mx);
    const float bK = RATIO_F * EPS_KF;

    zs[tid] = g_z[(size_t)cix * MFEAT + tid];

    float sacc[16][4];
    float iacc[8][4];
    #pragma unroll
    for (int nt = 0; nt < 16; ++nt)
        #pragma unroll
        for (int i = 0; i < 4; ++i) sacc[nt][i] = 0.f;
    #pragma unroll
    for (int nt = 0; nt < 8; ++nt)
        #pragma unroll
        for (int i = 0; i < 4; ++i) iacc[nt][i] = 0.f;

    float qzr = 0.f, sqr = 0.f;
    const float4* gq4 = reinterpret_cast<const float4*>(g_phi_q + base_row * MFEAT);
    const float4* gk4 = reinterpret_cast<const float4*>(g_phi_k + base_row * MFEAT);

    for (int h = 0; h < 2; ++h) {
        __syncthreads();
        const float4* Sg4 = reinterpret_cast<const float4*>(
            g_S + (size_t)cix * MFEAT * EDIM + (size_t)h * 128 * EDIM);
        #pragma unroll
        for (int j = 0; j < 4; ++j) {
            int r = wid * 4 + qr + 32 * j;
            #pragma unroll
            for (int i = 0; i < 4; ++i) {
                int c4 = qc + 8 * i;
                float4 tA = gq4[r * 64 + h * 32 + c4];
                float4 tB = gk4[r * 64 + h * 32 + c4];
                tA.x = tf32r(tA.x); tA.y = tf32r(tA.y); tA.z = tf32r(tA.z); tA.w = tf32r(tA.w);
                tB.x = tf32r(fmaf(aK, tB.x, bK)); tB.y = tf32r(fmaf(aK, tB.y, bK));
                tB.z = tf32r(fmaf(aK, tB.z, bK)); tB.w = tf32r(fmaf(aK, tB.w, bK));
                *reinterpret_cast<float4*>(bufA + r * SA + 4 * c4) = tA;
                *reinterpret_cast<float4*>(bufB + r * SA + 4 * c4) = tB;
            }
            #pragma unroll
            for (int i = 0; i < 2; ++i) {
                int c4 = qc + 8 * i;
                float4 tS = Sg4[r * 16 + c4];
                tS.x = tf32r(tS.x); tS.y = tf32r(tS.y); tS.z = tf32r(tS.z); tS.w = tf32r(tS.w);
                *reinterpret_cast<float4*>(bufS + r * SB + 4 * c4) = tS;
            }
        }
        __syncthreads();

        #pragma unroll 2
        for (int ks = 0; ks < 16; ++ks) {
            const int k0 = ks * 8;
            uint32_t a0 = F2U(bufA[(m0 + tq) * SA + k0 + tr]);
            uint32_t a1 = F2U(bufA[(m0 + tq + 8) * SA + k0 + tr]);
            uint32_t a2 = F2U(bufA[(m0 + tq) * SA + k0 + tr + 4]);
            uint32_t a3 = F2U(bufA[(m0 + tq + 8) * SA + k0 + tr + 4]);
            #pragma unroll
            for (int nt = 0; nt < 16; ++nt) {
                uint32_t b0 = F2U(bufB[(nt * 8 + tq) * SA + k0 + tr]);
                uint32_t b1 = F2U(bufB[(nt * 8 + tq) * SA + k0 + tr + 4]);
                mma8(sacc[nt], a0, a1, a2, a3, b0, b1);
            }
            #pragma unroll
            for (int nt = 0; nt < 8; ++nt) {
                uint32_t b0 = F2U(bufS[(k0 + tr) * SB + nt * 8 + tq]);
                uint32_t b1 = F2U(bufS[(k0 + tr + 4) * SB + nt * 8 + tq]);
                mma8(iacc[nt], a0, a1, a2, a3, b0, b1);
            }
        }
        {
            const float* pq = bufA + (tid >> 1) * SA + (tid & 1) * 64;
            const float* pz = zs + h * 128 + (tid & 1) * 64;
            #pragma unroll 8
            for (int j = 0; j < 64; ++j) {
                qzr = fmaf(pq[j], pz[j], qzr);
                sqr += pq[j];
            }
        }
    }

    __syncthreads();

    const int rlo = m0 + tq, rhi = rlo + 8;
    {
        float rsl = 0.f, rsh = 0.f;
        #pragma unroll
        for (int nt = 0; nt < 16; ++nt) {
            int c0 = nt * 8 + 2 * tr;
            float s0 = (c0     <= rlo) ? sacc[nt][0] : 0.f;
            float s1 = (c0 + 1 <= rlo) ? sacc[nt][1] : 0.f;
            float s2 = (c0     <= rhi) ? sacc[nt][2] : 0.f;
            float s3 = (c0 + 1 <= rhi) ? sacc[nt][3] : 0.f;
            rsl += s0 + s1; rsh += s2 + s3;
            *reinterpret_cast<float2*>(bufA + rlo * SA + c0) = make_float2(tf32r(s0), tf32r(s1));
            *reinterpret_cast<float2*>(bufA + rhi * SA + c0) = make_float2(tf32r(s2), tf32r(s3));
        }
        rsl += __shfl_xor_sync(0xffffffffu, rsl, 1);
        rsl += __shfl_xor_sync(0xffffffffu, rsl, 2);
        rsh += __shfl_xor_sync(0xffffffffu, rsh, 1);
        rsh += __shfl_xor_sync(0xffffffffu, rsh, 2);
        if (tr == 0) { sums[rlo] = rsl; sums[rhi] = rsh; }
    }
    {
        const float4* vg4 = reinterpret_cast<const float4*>(vin + base_row * EDIM);
        #pragma unroll
        for (int j = 0; j < 4; ++j) {
            int r = wid * 4 + qr + 32 * j;
            #pragma unroll
            for (int i = 0; i < 2; ++i) {
                int c4 = qc + 8 * i;
                float4 t = vg4[r * 16 + c4];
                t.x = tf32r(t.x); t.y = tf32r(t.y); t.z = tf32r(t.z); t.w = tf32r(t.w);
                *reinterpret_cast<float4*>(bufB + r * SB + 4 * c4) = t;
            }
        }
    }
    qz2[tid] = qzr; sq2[tid] = sqr;
    __syncthreads();

    if (tid < 128) {
        float d = qz2[2 * tid] + qz2[2 * tid + 1] + sums[tid]
                + EPS_DF * (sq2[2 * tid] + sq2[2 * tid + 1]);
        den[tid] = 1.f / d;
    }

    #pragma unroll 2
    for (int ks = 0; ks < 16; ++ks) {
        const int k0 = ks * 8;
        uint32_t a0 = F2U(bufA[(m0 + tq) * SA + k0 + tr]);
        uint32_t a1 = F2U(bufA[(m0 + tq + 8) * SA + k0 + tr]);
        uint32_t a2 = F2U(bufA[(m0 + tq) * SA + k0 + tr + 4]);
        uint32_t a3 = F2U(bufA[(m0 + tq + 8) * SA + k0 + tr + 4]);
        #pragma unroll
        for (int nt = 0; nt < 8; ++nt) {
            uint32_t b0 = F2U(bufB[(k0 + tr) * SB + nt * 8 + tq]);
            uint32_t b1 = F2U(bufB[(k0 + tr + 4) * SB + nt * 8 + tq]);
            mma8(iacc[nt], a0, a1, a2, a3, b0, b1);
        }
    }
    __syncthreads();

    {
        float il = den[rlo], ih = den[rhi];
        float* olo = outp + (base_row + rlo) * EDIM;
        float* ohi = outp + (base_row + rhi) * EDIM;
        #pragma unroll
        for (int nt = 0; nt < 8; ++nt) {
            int c0 = nt * 8 + 2 * tr;
            *reinterpret_cast<float2*>(olo + c0) = make_float2(iacc[nt][0] * il, iacc[nt][1] * il);
            *reinterpret_cast<float2*>(ohi + c0) = make_float2(iacc[nt][2] * ih, iacc[nt][3] * ih);
        }
    }
}

// ---------------------------------------------------------------------------
extern "C" void kernel_launch(void* const* d_in, const int* in_sizes, int n_in,
                              void* d_out, int out_size) {
    const float* big[3] = {nullptr, nullptr, nullptr};
    const float* proj = nullptr;
    int nb = 0;
    for (int i = 0; i < n_in; ++i) {
        if (in_sizes[i] == MFEAT * DDIM) proj = (const float*)d_in[i];
        else if (nb < 3) big[nb++] = (const float*)d_in[i];
    }
    const float* q = big[0];
    const float* k = big[1];
    const float* v = big[2];
    float* out = (float*)d_out;

    cudaFuncSetAttribute(phi_mma_kernel, cudaFuncAttributeMaxDynamicSharedMemorySize,
                         PHI_SMEMW * 4);
    cudaFuncSetAttribute(chunk_mma_kernel, cudaFuncAttributeMaxDynamicSharedMemorySize,
                         CK_SMEMF * (int)sizeof(float));
    cudaFuncSetAttribute(out_mma_kernel, cudaFuncAttributeMaxDynamicSharedMemorySize,
                         OUT_SMEMF * (int)sizeof(float));

    init_kmax_kernel<<<1, 32>>>();
    proj_prep_kernel<<<32, 256>>>(proj);
    phi_mma_kernel<<<BHC * NSEQ / 128, 512, PHI_SMEMW * 4>>>(q, 1);
    phi_mma_kernel<<<BHC * NSEQ / 128, 512, PHI_SMEMW * 4>>>(k, 0);
    chunk_mma_kernel<<<BHC * NCH, 256, CK_SMEMF * sizeof(float)>>>(v);
    prefix_kernel<<<(BHC * MFEAT * EDIM + BHC * MFEAT) / 256, 256>>>();
    out_mma_kernel<<<BHC * NCH, 256, OUT_SMEMF * sizeof(float)>>>(v, out);
}

// round 13
// speedup vs baseline: 1.2596x; 1.0002x over previous
#include <cuda_runtime.h>
#include <cuda_bf16.h>
#include <cstdint>
#include <math.h>

// Problem constants
#define BHC   16
#define NSEQ  4096
#define DDIM  64
#define MFEAT 256
#define EDIM  64
#define CHK   128
#define NCH   32

#define NORM_F   0.35355339059327373f
#define DIAG_C   0.0625f
#define RATIO_F  0.0625f
#define EPS_KF   1e-4f
#define EPS_DF   1e-6f

// Scratch (static device globals)
__device__ float    g_phi_q[BHC * NSEQ * MFEAT];   // 64 MiB
__device__ float    g_phi_k[BHC * NSEQ * MFEAT];   // 64 MiB (E = exp(dd - diag))
__device__ float    g_S[BHC * NCH * MFEAT * EDIM]; // 32 MiB
__device__ float    g_z[BHC * NCH * MFEAT];
__device__ unsigned g_kmax[BHC];
__device__ uint32_t g_pjh[MFEAT * DDIM / 2];       // packed bf16-hi pairs
__device__ uint32_t g_pjl[MFEAT * DDIM / 2];       // packed bf16-lo pairs

// ---------------------------------------------------------------------------
__device__ __forceinline__ float tf32r(float x) {
    uint32_t u;
    asm("cvt.rna.tf32.f32 %0, %1;" : "=r"(u) : "f"(x));
    return __uint_as_float(u);
}
#define F2U(x) __float_as_uint(x)

__device__ __forceinline__ void mma8(float* c, uint32_t a0, uint32_t a1,
                                     uint32_t a2, uint32_t a3,
                                     uint32_t b0, uint32_t b1) {
    asm volatile("mma.sync.aligned.m16n8k8.row.col.f32.tf32.tf32.f32 "
                 "{%0,%1,%2,%3},{%4,%5,%6,%7},{%8,%9},{%0,%1,%2,%3};"
                 : "+f"(c[0]), "+f"(c[1]), "+f"(c[2]), "+f"(c[3])
                 : "r"(a0), "r"(a1), "r"(a2), "r"(a3), "r"(b0), "r"(b1));
}

__device__ __forceinline__ void mma16b(float* c, uint32_t a0, uint32_t a1,
                                       uint32_t a2, uint32_t a3,
                                       uint32_t b0, uint32_t b1) {
    asm volatile("mma.sync.aligned.m16n8k16.row.col.f32.bf16.bf16.f32 "
                 "{%0,%1,%2,%3},{%4,%5,%6,%7},{%8,%9},{%0,%1,%2,%3};"
                 : "+f"(c[0]), "+f"(c[1]), "+f"(c[2]), "+f"(c[3])
                 : "r"(a0), "r"(a1), "r"(a2), "r"(a3), "r"(b0), "r"(b1));
}

__device__ __forceinline__ float decode_max(unsigned u) {
    return __uint_as_float((u & 0x80000000u) ? (u ^ 0x80000000u) : ~u);
}

__device__ __forceinline__ void split_pack(float a, float b, uint32_t& hi, uint32_t& lo) {
    __nv_bfloat16 ha = __float2bfloat16_rn(a);
    __nv_bfloat16 hb = __float2bfloat16_rn(b);
    __nv_bfloat16 la = __float2bfloat16_rn(a - __bfloat162float(ha));
    __nv_bfloat16 lb = __float2bfloat16_rn(b - __bfloat162float(hb));
    __nv_bfloat162 hv = __halves2bfloat162(ha, hb);
    __nv_bfloat162 lv = __halves2bfloat162(la, lb);
    hi = *reinterpret_cast<uint32_t*>(&hv);
    lo = *reinterpret_cast<uint32_t*>(&lv);
}

// ---------------------------------------------------------------------------
__global__ void init_kmax_kernel() {
    if (threadIdx.x < BHC) g_kmax[threadIdx.x] = 0u;
}

__global__ void proj_prep_kernel(const float* __restrict__ proj) {
    int idx = blockIdx.x * blockDim.x + threadIdx.x;   // pair index
    if (idx < MFEAT * DDIM / 2) {
        float a = proj[2 * idx] * NORM_F;
        float b = proj[2 * idx + 1] * NORM_F;
        uint32_t h, l;
        split_pack(a, b, h, l);
        g_pjh[idx] = h;
        g_pjl[idx] = l;
    }
}

// ---------------------------------------------------------------------------
// phi via split-bf16 mma (hi*hi + hi*lo + lo*hi), 512 threads.  (R12 winner)
#define PH_QH  0
#define PH_QL  4608
#define PH_PHB 9216
#define PH_PLB 18432
#define PH_PMAX 27648           // [128][8]
#define PH_DSUM 28672           // [256]
#define PH_RMAX 28928           // [128]
#define PHI_SMEMW 29056

__global__ void __launch_bounds__(512, 1)
phi_mma_kernel(const float* __restrict__ data, int is_query) {
    extern __shared__ uint32_t su[];
    uint32_t* qhb = su + PH_QH;       // [128][36] packed bf16 pairs
    uint32_t* qlb = su + PH_QL;
    uint32_t* phb = su + PH_PHB;      // [256][36]
    uint32_t* plb = su + PH_PLB;
    float* pmax = reinterpret_cast<float*>(su + PH_PMAX);
    float* dsum = reinterpret_cast<float*>(su + PH_DSUM);
    float* rmax = reinterpret_cast<float*>(su + PH_RMAX);

    const int tid = threadIdx.x;
    const int wid = tid >> 5, lane = tid & 31;
    const int tq = lane >> 2, tr = lane & 3;
    const int wg_n = wid & 7, wg_m = wid >> 3;
    const size_t base = (size_t)blockIdx.x * 128;
    float* outg = is_query ? g_phi_q : g_phi_k;

    {
        const float4* src = reinterpret_cast<const float4*>(data + base * DDIM);
        #pragma unroll
        for (int i = 0; i < 4; ++i) {
            int idx = tid + i * 512;
            int r = idx >> 4, c4 = idx & 15;
            float4 t = src[idx];
            uint32_t h0, l0, h1, l1;
            split_pack(t.x, t.y, h0, l0);
            split_pack(t.z, t.w, h1, l1);
            *reinterpret_cast<uint2*>(qhb + r * 36 + 2 * c4) = make_uint2(h0, h1);
            *reinterpret_cast<uint2*>(qlb + r * 36 + 2 * c4) = make_uint2(l0, l1);
        }
    }
    {
        const uint4* sh = reinterpret_cast<const uint4*>(g_pjh);
        const uint4* sl = reinterpret_cast<const uint4*>(g_pjl);
        #pragma unroll
        for (int i = 0; i < 4; ++i) {
            int idx = tid + i * 512;
            int r = idx >> 3, k4 = idx & 7;
            *reinterpret_cast<uint4*>(phb + r * 36 + 4 * k4) = sh[idx];
            *reinterpret_cast<uint4*>(plb + r * 36 + 4 * k4) = sl[idx];
        }
    }
    __syncthreads();

    if (tid < 256) {
        int r = tid >> 1, hf = tid & 1;
        float s = 0.f;
        #pragma unroll 8
        for (int c = 0; c < 16; ++c) {
            uint32_t hu = qhb[r * 36 + hf * 16 + c];
            uint32_t lu = qlb[r * 36 + hf * 16 + c];
            float2 h = __bfloat1622float2(*reinterpret_cast<__nv_bfloat162*>(&hu));
            float2 l = __bfloat1622float2(*reinterpret_cast<__nv_bfloat162*>(&lu));
            float x0 = h.x + l.x, x1 = h.y + l.y;
            s = fmaf(x0, x0, fmaf(x1, x1, s));
        }
        dsum[tid] = s;
    }

    float acc[4][4][4];
    #pragma unroll
    for (int mt = 0; mt < 4; ++mt)
        #pragma unroll
        for (int nt = 0; nt < 4; ++nt)
            #pragma unroll
            for (int i = 0; i < 4; ++i) acc[mt][nt][i] = 0.f;

    const int nbase = wg_n * 32 + tq;
    #pragma unroll
    for (int ki = 0; ki < 4; ++ki) {
        const int kp0 = ki * 8;
        uint32_t bh0[4], bh1[4], bl0[4], bl1[4];
        #pragma unroll
        for (int nt = 0; nt < 4; ++nt) {
            int n = nbase + nt * 8;
            bh0[nt] = phb[n * 36 + kp0 + tr];
            bh1[nt] = phb[n * 36 + kp0 + tr + 4];
            bl0[nt] = plb[n * 36 + kp0 + tr];
            bl1[nt] = plb[n * 36 + kp0 + tr + 4];
        }
        #pragma unroll
        for (int mt = 0; mt < 4; ++mt) {
            const int r0 = (wg_m * 4 + mt) * 16;
            uint32_t ah0 = qhb[(r0 + tq) * 36 + kp0 + tr];
            uint32_t ah1 = qhb[(r0 + tq + 8) * 36 + kp0 + tr];
            uint32_t ah2 = qhb[(r0 + tq) * 36 + kp0 + tr + 4];
            uint32_t ah3 = qhb[(r0 + tq + 8) * 36 + kp0 + tr + 4];
            uint32_t al0 = qlb[(r0 + tq) * 36 + kp0 + tr];
            uint32_t al1 = qlb[(r0 + tq + 8) * 36 + kp0 + tr];
            uint32_t al2 = qlb[(r0 + tq) * 36 + kp0 + tr + 4];
            uint32_t al3 = qlb[(r0 + tq + 8) * 36 + kp0 + tr + 4];
            #pragma unroll
            for (int nt = 0; nt < 4; ++nt) {
                mma16b(acc[mt][nt], ah0, ah1, ah2, ah3, bh0[nt], bh1[nt]);
                mma16b(acc[mt][nt], ah0, ah1, ah2, ah3, bl0[nt], bl1[nt]);
                mma16b(acc[mt][nt], al0, al1, al2, al3, bh0[nt], bh1[nt]);
            }
        }
    }

    #pragma unroll
    for (int mt = 0; mt < 4; ++mt) {
        const int rA = (wg_m * 4 + mt) * 16 + tq, rB = rA + 8;
        float mA = -3.4e38f, mB = -3.4e38f;
        #pragma unroll
        for (int nt = 0; nt < 4; ++nt) {
            mA = fmaxf(mA, fmaxf(acc[mt][nt][0], acc[mt][nt][1]));
            mB = fmaxf(mB, fmaxf(acc[mt][nt][2], acc[mt][nt][3]));
        }
        mA = fmaxf(mA, __shfl_xor_sync(0xffffffffu, mA, 1));
        mA = fmaxf(mA, __shfl_xor_sync(0xffffffffu, mA, 2));
        mB = fmaxf(mB, __shfl_xor_sync(0xffffffffu, mB, 1));
        mB = fmaxf(mB, __shfl_xor_sync(0xffffffffu, mB, 2));
        if (tr == 0) {
            pmax[rA * 8 + wg_n] = mA;
            pmax[rB * 8 + wg_n] = mB;
        }
    }
    __syncthreads();

    if (tid < 128) {
        float m = pmax[tid * 8];
        #pragma unroll
        for (int w = 1; w < 8; ++w) m = fmaxf(m, pmax[tid * 8 + w]);
        rmax[tid] = m;
    }
    __syncthreads();

    if (!is_query && wid == 0) {
        float m = -3.4e38f;
        #pragma unroll
        for (int i = 0; i < 4; ++i) m = fmaxf(m, rmax[lane * 4 + i]);
        #pragma unroll
        for (int o = 16; o > 0; o >>= 1)
            m = fmaxf(m, __shfl_xor_sync(0xffffffffu, m, o));
        if (lane == 0) {
            unsigned u = __float_as_uint(m);
            u = (u & 0x80000000u) ? ~u : (u | 0x80000000u);
            atomicMax(&g_kmax[blockIdx.x >> 5], u);
        }
    }

    #pragma unroll
    for (int mt = 0; mt < 4; ++mt) {
        const int rA = (wg_m * 4 + mt) * 16 + tq, rB = rA + 8;
        float offA = DIAG_C * (dsum[2 * rA] + dsum[2 * rA + 1]);
        float offB = DIAG_C * (dsum[2 * rB] + dsum[2 * rB + 1]);
        if (is_query) { offA += rmax[rA]; offB += rmax[rB]; }
        float* oA = outg + (base + rA) * MFEAT + wg_n * 32;
        float* oB = outg + (base + rB) * MFEAT + wg_n * 32;
        #pragma unroll
        for (int nt = 0; nt < 4; ++nt) {
            int c0 = nt * 8 + 2 * tr;
            float v0, v1, v2, v3;
            if (is_query) {
                v0 = RATIO_F * (__expf(acc[mt][nt][0] - offA) + EPS_KF);
                v1 = RATIO_F * (__expf(acc[mt][nt][1] - offA) + EPS_KF);
                v2 = RATIO_F * (__expf(acc[mt][nt][2] - offB) + EPS_KF);
                v3 = RATIO_F * (__expf(acc[mt][nt][3] - offB) + EPS_KF);
            } else {
                v0 = __expf(acc[mt][nt][0] - offA);
                v1 = __expf(acc[mt][nt][1] - offA);
                v2 = __expf(acc[mt][nt][2] - offB);
                v3 = __expf(acc[mt][nt][3] - offB);
            }
            *reinterpret_cast<float2*>(oA + c0) = make_float2(v0, v1);
            *reinterpret_cast<float2*>(oB + c0) = make_float2(v2, v3);
        }
    }
}

// ---------------------------------------------------------------------------
// chunk sums via mma: 2 CTAs per chunk (m-halves), 256 threads, 2 CTAs/SM.
// CTA half h: C[m in 128h..128h+128, e 64(+z)] = phik^T @ [v|1]
#define CKS 136                     // stride, 136 % 32 == 8 -> conflict-free a-frags
#define CK_VSO (128 * CKS)
#define CK_SMEMF (CK_VSO + 128 * 72)
__global__ void __launch_bounds__(256, 2)
chunk_mma_kernel(const float* __restrict__ vin) {
    extern __shared__ float sf[];
    float* ksm = sf;                 // [128 k][128 m-local]
    float* vsm = sf + CK_VSO;        // [128 k][72]

    const int tid = threadIdx.x;
    const int wid = tid >> 5, lane = tid & 31;
    const int tq = lane >> 2, tr = lane & 3;
    const int bix = blockIdx.x;
    const int cix = bix >> 1;
    const int mhalf = bix & 1;
    const size_t base_row = (size_t)(cix / NCH) * NSEQ + (size_t)(cix % NCH) * CHK;

    const float mx = decode_max(g_kmax[cix >> 5]);
    const float aK = RATIO_F * __expf(-mx);
    const float bK = RATIO_F * EPS_KF;

    // stage phi_k half-columns [128 r][128 m] (affine -> tf32)
    {
        const float4* src = reinterpret_cast<const float4*>(g_phi_k + base_row * MFEAT);
        #pragma unroll
        for (int i = 0; i < 16; ++i) {
            int idx = tid + i * 256;          // 4096 float4
            int r = idx >> 5, c4 = idx & 31;
            float4 t = src[r * 64 + mhalf * 32 + c4];
            t.x = tf32r(fmaf(aK, t.x, bK)); t.y = tf32r(fmaf(aK, t.y, bK));
            t.z = tf32r(fmaf(aK, t.z, bK)); t.w = tf32r(fmaf(aK, t.w, bK));
            *reinterpret_cast<float4*>(ksm + r * CKS + 4 * c4) = t;
        }
    }
    // stage v [128][64] + ones column
    {
        const float4* src = reinterpret_cast<const float4*>(vin + base_row * EDIM);
        #pragma unroll
        for (int i = 0; i < 8; ++i) {
            int idx = tid + i * 256;          // 2048 float4
            int r = idx >> 4, c4 = idx & 15;
            float4 t = src[idx];
            t.x = tf32r(t.x); t.y = tf32r(t.y); t.z = tf32r(t.z); t.w = tf32r(t.w);
            *reinterpret_cast<float4*>(vsm + r * 72 + 4 * c4) = t;
        }
        if (tid < 128) {
            *reinterpret_cast<float4*>(vsm + tid * 72 + 64) = make_float4(1.f, 0.f, 0.f, 0.f);
            *reinterpret_cast<float4*>(vsm + tid * 72 + 68) = make_float4(0.f, 0.f, 0.f, 0.f);
        }
    }
    __syncthreads();

    const int m0 = wid * 16;                  // local m-tile
    float acc[9][4];
    #pragma unroll
    for (int nt = 0; nt < 9; ++nt)
        #pragma unroll
        for (int i = 0; i < 4; ++i) acc[nt][i] = 0.f;

    #pragma unroll 4
    for (int ks = 0; ks < 16; ++ks) {
        const int k0 = ks * 8;
        uint32_t a0 = F2U(ksm[(k0 + tr) * CKS + m0 + tq]);
        uint32_t a1 = F2U(ksm[(k0 + tr) * CKS + m0 + tq + 8]);
        uint32_t a2 = F2U(ksm[(k0 + tr + 4) * CKS + m0 + tq]);
        uint32_t a3 = F2U(ksm[(k0 + tr + 4) * CKS + m0 + tq + 8]);
        #pragma unroll
        for (int nt = 0; nt < 9; ++nt) {
            uint32_t b0 = F2U(vsm[(k0 + tr) * 72 + nt * 8 + tq]);
            uint32_t b1 = F2U(vsm[(k0 + tr + 4) * 72 + nt * 8 + tq]);
            mma8(acc[nt], a0, a1, a2, a3, b0, b1);
        }
    }

    float* Sg = g_S + (size_t)cix * MFEAT * EDIM;
    float* zg = g_z + (size_t)cix * MFEAT;
    {
        int m = mhalf * 128 + m0 + tq;
        #pragma unroll
        for (int nt = 0; nt < 8; ++nt) {
            int c0 = nt * 8 + 2 * tr;
            *reinterpret_cast<float2*>(Sg + m * EDIM + c0)
                = make_float2(acc[nt][0], acc[nt][1]);
            *reinterpret_cast<float2*>(Sg + (m + 8) * EDIM + c0)
                = make_float2(acc[nt][2], acc[nt][3]);
        }
        if (tr == 0) {
            zg[m]     = acc[8][0];
            zg[m + 8] = acc[8][2];
        }
    }
}

// ---------------------------------------------------------------------------
__global__ void prefix_kernel() {
    const int idx = blockIdx.x * blockDim.x + threadIdx.x;
    const int T1 = BHC * MFEAT * EDIM;
    if (idx < T1) {
        int bh = idx / (MFEAT * EDIM);
        int rem = idx % (MFEAT * EDIM);
        size_t base = (size_t)bh * NCH * MFEAT * EDIM + rem;
        float run = 0.f;
        #pragma unroll
        for (int c = 0; c < NCH; ++c) {
            size_t p = base + (size_t)c * MFEAT * EDIM;
            float t = g_S[p]; g_S[p] = run; run += t;
        }
    } else if (idx < T1 + BHC * MFEAT) {
        int j = idx - T1;
        int bh = j / MFEAT;
        int rem = j % MFEAT;
        size_t base = (size_t)bh * NCH * MFEAT + rem;
        float run = 0.f;
        #pragma unroll
        for (int c = 0; c < NCH; ++c) {
            size_t p = base + (size_t)c * MFEAT;
            float t = g_z[p]; g_z[p] = run; run += t;
        }
    }
}

// ---------------------------------------------------------------------------
// out kernel (256 threads) with causal n-tile skip, SMSP-balanced:
//   m-tile = (wid<4) ? wid : 11-wid; score n-tile groups = (mt_t+2)>>1 of 4.
#define SA 140
#define SB 72
#define BUFA 0
#define BUFB (128 * SA)
#define BUFS (2 * 128 * SA)
#define ZSO  (BUFS + 128 * SB)
#define QZ2O (ZSO + 256)
#define SQ2O (QZ2O + 256)
#define SUMO (SQ2O + 256)
#define DENO (SUMO + 128)
#define OUT_SMEMF (DENO + 128)

__global__ void __launch_bounds__(256, 1)
out_mma_kernel(const float* __restrict__ vin, float* __restrict__ outp) {
    extern __shared__ float sf[];
    float* bufA = sf + BUFA;
    float* bufB = sf + BUFB;
    float* bufS = sf + BUFS;
    float* zs   = sf + ZSO;
    float* qz2  = sf + QZ2O;
    float* sq2  = sf + SQ2O;
    float* sums = sf + SUMO;
    float* den  = sf + DENO;

    const int tid = threadIdx.x;
    const int wid = tid >> 5, lane = tid & 31;
    const int tq = lane >> 2, tr = lane & 3;
    const int qr = lane >> 3, qc = lane & 7;
    const int cix = blockIdx.x;
    const size_t base_row = (size_t)(cix / NCH) * NSEQ + (size_t)(cix % NCH) * CHK;

    // SMSP-balanced causal tile permutation
    const int mt_t = (wid < 4) ? wid : 11 - wid;
    const int m0 = mt_t * 16;
    const int ngroups = (mt_t + 2) >> 1;    // groups of 4 score n-tiles needed

    const float mx = decode_max(g_kmax[cix >> 5]);
    const float aK = RATIO_F * __expf(-mx);
    const float bK = RATIO_F * EPS_KF;

    zs[tid] = g_z[(size_t)cix * MFEAT + tid];

    float sacc[16][4];
    float iacc[8][4];
    #pragma unroll
    for (int nt = 0; nt < 16; ++nt)
        #pragma unroll
        for (int i = 0; i < 4; ++i) sacc[nt][i] = 0.f;
    #pragma unroll
    for (int nt = 0; nt < 8; ++nt)
        #pragma unroll
        for (int i = 0; i < 4; ++i) iacc[nt][i] = 0.f;

    float qzr = 0.f, sqr = 0.f;
    const float4* gq4 = reinterpret_cast<const float4*>(g_phi_q + base_row * MFEAT);
    const float4* gk4 = reinterpret_cast<const float4*>(g_phi_k + base_row * MFEAT);

    for (int h = 0; h < 2; ++h) {
        __syncthreads();
        const float4* Sg4 = reinterpret_cast<const float4*>(
            g_S + (size_t)cix * MFEAT * EDIM + (size_t)h * 128 * EDIM);
        #pragma unroll
        for (int j = 0; j < 4; ++j) {
            int r = wid * 4 + qr + 32 * j;
            #pragma unroll
            for (int i = 0; i < 4; ++i) {
                int c4 = qc + 8 * i;
                float4 tA = gq4[r * 64 + h * 32 + c4];
                float4 tB = gk4[r * 64 + h * 32 + c4];
                tA.x = tf32r(tA.x); tA.y = tf32r(tA.y); tA.z = tf32r(tA.z); tA.w = tf32r(tA.w);
                tB.x = tf32r(fmaf(aK, tB.x, bK)); tB.y = tf32r(fmaf(aK, tB.y, bK));
                tB.z = tf32r(fmaf(aK, tB.z, bK)); tB.w = tf32r(fmaf(aK, tB.w, bK));
                *reinterpret_cast<float4*>(bufA + r * SA + 4 * c4) = tA;
                *reinterpret_cast<float4*>(bufB + r * SA + 4 * c4) = tB;
            }
            #pragma unroll
            for (int i = 0; i < 2; ++i) {
                int c4 = qc + 8 * i;
                float4 tS = Sg4[r * 16 + c4];
                tS.x = tf32r(tS.x); tS.y = tf32r(tS.y); tS.z = tf32r(tS.z); tS.w = tf32r(tS.w);
                *reinterpret_cast<float4*>(bufS + r * SB + 4 * c4) = tS;
            }
        }
        __syncthreads();

        #pragma unroll 2
        for (int ks = 0; ks < 16; ++ks) {
            const int k0 = ks * 8;
            uint32_t a0 = F2U(bufA[(m0 + tq) * SA + k0 + tr]);
            uint32_t a1 = F2U(bufA[(m0 + tq + 8) * SA + k0 + tr]);
            uint32_t a2 = F2U(bufA[(m0 + tq) * SA + k0 + tr + 4]);
            uint32_t a3 = F2U(bufA[(m0 + tq + 8) * SA + k0 + tr + 4]);
            #pragma unroll
            for (int g = 0; g < 4; ++g) {
                if (g < ngroups) {             // warp-uniform branch
                    #pragma unroll
                    for (int j = 0; j < 4; ++j) {
                        const int nt = g * 4 + j;
                        uint32_t b0 = F2U(bufB[(nt * 8 + tq) * SA + k0 + tr]);
                        uint32_t b1 = F2U(bufB[(nt * 8 + tq) * SA + k0 + tr + 4]);
                        mma8(sacc[nt], a0, a1, a2, a3, b0, b1);
                    }
                }
            }
            #pragma unroll
            for (int nt = 0; nt < 8; ++nt) {
                uint32_t b0 = F2U(bufS[(k0 + tr) * SB + nt * 8 + tq]);
                uint32_t b1 = F2U(bufS[(k0 + tr + 4) * SB + nt * 8 + tq]);
                mma8(iacc[nt], a0, a1, a2, a3, b0, b1);
            }
        }
        {
            const float* pq = bufA + (tid >> 1) * SA + (tid & 1) * 64;
            const float* pz = zs + h * 128 + (tid & 1) * 64;
            #pragma unroll 8
            for (int j = 0; j < 64; ++j) {
                qzr = fmaf(pq[j], pz[j], qzr);
                sqr += pq[j];
            }
        }
    }

    __syncthreads();

    const int rlo = m0 + tq, rhi = rlo + 8;
    {
        float rsl = 0.f, rsh = 0.f;
        #pragma unroll
        for (int nt = 0; nt < 16; ++nt) {
            int c0 = nt * 8 + 2 * tr;
            float s0 = (c0     <= rlo) ? sacc[nt][0] : 0.f;
            float s1 = (c0 + 1 <= rlo) ? sacc[nt][1] : 0.f;
            float s2 = (c0     <= rhi) ? sacc[nt][2] : 0.f;
            float s3 = (c0 + 1 <= rhi) ? sacc[nt][3] : 0.f;
            rsl += s0 + s1; rsh += s2 + s3;
            *reinterpret_cast<float2*>(bufA + rlo * SA + c0) = make_float2(tf32r(s0), tf32r(s1));
            *reinterpret_cast<float2*>(bufA + rhi * SA + c0) = make_float2(tf32r(s2), tf32r(s3));
        }
        rsl += __shfl_xor_sync(0xffffffffu, rsl, 1);
        rsl += __shfl_xor_sync(0xffffffffu, rsl, 2);
        rsh += __shfl_xor_sync(0xffffffffu, rsh, 1);
        rsh += __shfl_xor_sync(0xffffffffu, rsh, 2);
        if (tr == 0) { sums[rlo] = rsl; sums[rhi] = rsh; }
    }
    {
        const float4* vg4 = reinterpret_cast<const float4*>(vin + base_row * EDIM);
        #pragma unroll
        for (int j = 0; j < 4; ++j) {
            int r = wid * 4 + qr + 32 * j;
            #pragma unroll
            for (int i = 0; i < 2; ++i) {
                int c4 = qc + 8 * i;
                float4 t = vg4[r * 16 + c4];
                t.x = tf32r(t.x); t.y = tf32r(t.y); t.z = tf32r(t.z); t.w = tf32r(t.w);
                *reinterpret_cast<float4*>(bufB + r * SB + 4 * c4) = t;
            }
        }
    }
    qz2[tid] = qzr; sq2[tid] = sqr;
    __syncthreads();

    if (tid < 128) {
        float d = qz2[2 * tid] + qz2[2 * tid + 1] + sums[tid]
                + EPS_DF * (sq2[2 * tid] + sq2[2 * tid + 1]);
        den[tid] = 1.f / d;
    }

    // intra: iacc += masked_scores @ v  (rows of bufA beyond tril are zeros)
    #pragma unroll 2
    for (int ks = 0; ks < 16; ++ks) {
        const int k0 = ks * 8;
        uint32_t a0 = F2U(bufA[(m0 + tq) * SA + k0 + tr]);
        uint32_t a1 = F2U(bufA[(m0 + tq + 8) * SA + k0 + tr]);
        uint32_t a2 = F2U(bufA[(m0 + tq) * SA + k0 + tr + 4]);
        uint32_t a3 = F2U(bufA[(m0 + tq + 8) * SA + k0 + tr + 4]);
        #pragma unroll
        for (int nt = 0; nt < 8; ++nt) {
            uint32_t b0 = F2U(bufB[(k0 + tr) * SB + nt * 8 + tq]);
            uint32_t b1 = F2U(bufB[(k0 + tr + 4) * SB + nt * 8 + tq]);
            mma8(iacc[nt], a0, a1, a2, a3, b0, b1);
        }
    }
    __syncthreads();

    {
        float il = den[rlo], ih = den[rhi];
        float* olo = outp + (base_row + rlo) * EDIM;
        float* ohi = outp + (base_row + rhi) * EDIM;
        #pragma unroll
        for (int nt = 0; nt < 8; ++nt) {
            int c0 = nt * 8 + 2 * tr;
            *reinterpret_cast<float2*>(olo + c0) = make_float2(iacc[nt][0] * il, iacc[nt][1] * il);
            *reinterpret_cast<float2*>(ohi + c0) = make_float2(iacc[nt][2] * ih, iacc[nt][3] * ih);
        }
    }
}

// ---------------------------------------------------------------------------
extern "C" void kernel_launch(void* const* d_in, const int* in_sizes, int n_in,
                              void* d_out, int out_size) {
    const float* big[3] = {nullptr, nullptr, nullptr};
    const float* proj = nullptr;
    int nb = 0;
    for (int i = 0; i < n_in; ++i) {
        if (in_sizes[i] == MFEAT * DDIM) proj = (const float*)d_in[i];
        else if (nb < 3) big[nb++] = (const float*)d_in[i];
    }
    const float* q = big[0];
    const float* k = big[1];
    const float* v = big[2];
    float* out = (float*)d_out;

    cudaFuncSetAttribute(phi_mma_kernel, cudaFuncAttributeMaxDynamicSharedMemorySize,
                         PHI_SMEMW * 4);
    cudaFuncSetAttribute(chunk_mma_kernel, cudaFuncAttributeMaxDynamicSharedMemorySize,
                         CK_SMEMF * (int)sizeof(float));
    cudaFuncSetAttribute(out_mma_kernel, cudaFuncAttributeMaxDynamicSharedMemorySize,
                         OUT_SMEMF * (int)sizeof(float));

    init_kmax_kernel<<<1, 32>>>();
    proj_prep_kernel<<<32, 256>>>(proj);
    phi_mma_kernel<<<BHC * NSEQ / 128, 512, PHI_SMEMW * 4>>>(q, 1);
    phi_mma_kernel<<<BHC * NSEQ / 128, 512, PHI_SMEMW * 4>>>(k, 0);
    chunk_mma_kernel<<<BHC * NCH * 2, 256, CK_SMEMF * sizeof(float)>>>(v);
    prefix_kernel<<<(BHC * MFEAT * EDIM + BHC * MFEAT) / 256, 256>>>();
    out_mma_kernel<<<BHC * NCH, 256, OUT_SMEMF * sizeof(float)>>>(v, out);
}

// round 16
// speedup vs baseline: 1.2734x; 1.0109x over previous
#include <cuda_runtime.h>
#include <cuda_bf16.h>
#include <cstdint>
#include <math.h>

// Problem constants
#define BHC   16
#define NSEQ  4096
#define DDIM  64
#define MFEAT 256
#define EDIM  64
#define CHK   128
#define NCH   32

#define NORM_F   0.35355339059327373f
#define DIAG_C   0.0625f
#define RATIO_F  0.0625f
#define EPS_KF   1e-4f
#define EPS_DF   1e-6f

// Scratch (static device globals)
__device__ float    g_phi_q[BHC * NSEQ * MFEAT];   // 64 MiB
__device__ float    g_phi_k[BHC * NSEQ * MFEAT];   // 64 MiB (E = exp(dd - diag))
__device__ float    g_S[BHC * NCH * MFEAT * EDIM]; // 32 MiB
__device__ float    g_z[BHC * NCH * MFEAT];
__device__ unsigned g_kmax[BHC];
__device__ uint32_t g_pjh[MFEAT * DDIM / 2];       // packed bf16-hi pairs
__device__ uint32_t g_pjl[MFEAT * DDIM / 2];       // packed bf16-lo pairs

// ---------------------------------------------------------------------------
__device__ __forceinline__ float tf32r(float x) {
    uint32_t u;
    asm("cvt.rna.tf32.f32 %0, %1;" : "=r"(u) : "f"(x));
    return __uint_as_float(u);
}
#define F2U(x) __float_as_uint(x)

__device__ __forceinline__ uint32_t smem_u32(const void* p) {
    return (uint32_t)__cvta_generic_to_shared(p);
}

__device__ __forceinline__ void ldsm_x4(uint32_t& d0, uint32_t& d1,
                                        uint32_t& d2, uint32_t& d3, uint32_t addr) {
    asm volatile("ldmatrix.sync.aligned.m8n8.x4.shared.b16 {%0,%1,%2,%3}, [%4];"
                 : "=r"(d0), "=r"(d1), "=r"(d2), "=r"(d3) : "r"(addr));
}

__device__ __forceinline__ void mma8(float* c, uint32_t a0, uint32_t a1,
                                     uint32_t a2, uint32_t a3,
                                     uint32_t b0, uint32_t b1) {
    asm volatile("mma.sync.aligned.m16n8k8.row.col.f32.tf32.tf32.f32 "
                 "{%0,%1,%2,%3},{%4,%5,%6,%7},{%8,%9},{%0,%1,%2,%3};"
                 : "+f"(c[0]), "+f"(c[1]), "+f"(c[2]), "+f"(c[3])
                 : "r"(a0), "r"(a1), "r"(a2), "r"(a3), "r"(b0), "r"(b1));
}

__device__ __forceinline__ void mma16b(float* c, uint32_t a0, uint32_t a1,
                                       uint32_t a2, uint32_t a3,
                                       uint32_t b0, uint32_t b1) {
    asm volatile("mma.sync.aligned.m16n8k16.row.col.f32.bf16.bf16.f32 "
                 "{%0,%1,%2,%3},{%4,%5,%6,%7},{%8,%9},{%0,%1,%2,%3};"
                 : "+f"(c[0]), "+f"(c[1]), "+f"(c[2]), "+f"(c[3])
                 : "r"(a0), "r"(a1), "r"(a2), "r"(a3), "r"(b0), "r"(b1));
}

__device__ __forceinline__ float decode_max(unsigned u) {
    return __uint_as_float((u & 0x80000000u) ? (u ^ 0x80000000u) : ~u);
}

__device__ __forceinline__ void split_pack(float a, float b, uint32_t& hi, uint32_t& lo) {
    __nv_bfloat16 ha = __float2bfloat16_rn(a);
    __nv_bfloat16 hb = __float2bfloat16_rn(b);
    __nv_bfloat16 la = __float2bfloat16_rn(a - __bfloat162float(ha));
    __nv_bfloat16 lb = __float2bfloat16_rn(b - __bfloat162float(hb));
    __nv_bfloat162 hv = __halves2bfloat162(ha, hb);
    __nv_bfloat162 lv = __halves2bfloat162(la, lb);
    hi = *reinterpret_cast<uint32_t*>(&hv);
    lo = *reinterpret_cast<uint32_t*>(&lv);
}

// ---------------------------------------------------------------------------
__global__ void init_kmax_kernel() {
    if (threadIdx.x < BHC) g_kmax[threadIdx.x] = 0u;
}

__global__ void proj_prep_kernel(const float* __restrict__ proj) {
    int idx = blockIdx.x * blockDim.x + threadIdx.x;   // pair index
    if (idx < MFEAT * DDIM / 2) {
        float a = proj[2 * idx] * NORM_F;
        float b = proj[2 * idx + 1] * NORM_F;
        uint32_t h, l;
        split_pack(a, b, h, l);
        g_pjh[idx] = h;
        g_pjl[idx] = l;
    }
}

// ---------------------------------------------------------------------------
// phi via split-bf16 mma + ldmatrix fragment loads, 512 threads.
#define PH_QH  0
#define PH_QL  4608
#define PH_PHB 9216
#define PH_PLB 18432
#define PH_PMAX 27648           // [128][8]
#define PH_DSUM 28672           // [256]
#define PH_RMAX 28928           // [128]
#define PHI_SMEMW 29056

__global__ void __launch_bounds__(512, 1)
phi_mma_kernel(const float* __restrict__ data, int is_query) {
    extern __shared__ uint32_t su[];
    uint32_t* qhb = su + PH_QH;       // [128][36] packed bf16 pairs
    uint32_t* qlb = su + PH_QL;
    uint32_t* phb = su + PH_PHB;      // [256][36]
    uint32_t* plb = su + PH_PLB;
    float* pmax = reinterpret_cast<float*>(su + PH_PMAX);
    float* dsum = reinterpret_cast<float*>(su + PH_DSUM);
    float* rmax = reinterpret_cast<float*>(su + PH_RMAX);

    const int tid = threadIdx.x;
    const int wid = tid >> 5, lane = tid & 31;
    const int tq = lane >> 2, tr = lane & 3;
    const int wg_n = wid & 7, wg_m = wid >> 3;
    const size_t base = (size_t)blockIdx.x * 128;
    float* outg = is_query ? g_phi_q : g_phi_k;

    {
        const float4* src = reinterpret_cast<const float4*>(data + base * DDIM);
        #pragma unroll
        for (int i = 0; i < 4; ++i) {
            int idx = tid + i * 512;
            int r = idx >> 4, c4 = idx & 15;
            float4 t = src[idx];
            uint32_t h0, l0, h1, l1;
            split_pack(t.x, t.y, h0, l0);
            split_pack(t.z, t.w, h1, l1);
            *reinterpret_cast<uint2*>(qhb + r * 36 + 2 * c4) = make_uint2(h0, h1);
            *reinterpret_cast<uint2*>(qlb + r * 36 + 2 * c4) = make_uint2(l0, l1);
        }
    }
    {
        const uint4* sh = reinterpret_cast<const uint4*>(g_pjh);
        const uint4* sl = reinterpret_cast<const uint4*>(g_pjl);
        #pragma unroll
        for (int i = 0; i < 4; ++i) {
            int idx = tid + i * 512;
            int r = idx >> 3, k4 = idx & 7;
            *reinterpret_cast<uint4*>(phb + r * 36 + 4 * k4) = sh[idx];
            *reinterpret_cast<uint4*>(plb + r * 36 + 4 * k4) = sl[idx];
        }
    }
    __syncthreads();

    if (tid < 256) {
        int r = tid >> 1, hf = tid & 1;
        float s = 0.f;
        #pragma unroll 8
        for (int c = 0; c < 16; ++c) {
            uint32_t hu = qhb[r * 36 + hf * 16 + c];
            uint32_t lu = qlb[r * 36 + hf * 16 + c];
            float2 h = __bfloat1622float2(*reinterpret_cast<__nv_bfloat162*>(&hu));
            float2 l = __bfloat1622float2(*reinterpret_cast<__nv_bfloat162*>(&lu));
            float x0 = h.x + l.x, x1 = h.y + l.y;
            s = fmaf(x0, x0, fmaf(x1, x1, s));
        }
        dsum[tid] = s;
    }

    float acc[4][4][4];
    #pragma unroll
    for (int mt = 0; mt < 4; ++mt)
        #pragma unroll
        for (int nt = 0; nt < 4; ++nt)
            #pragma unroll
            for (int i = 0; i < 4; ++i) acc[mt][nt][i] = 0.f;

    // ldmatrix lane-address offsets (in uint32 words)
    // A x4: sub0 rows r0..r0+7 @kp0, sub1 rows+8 @kp0, sub2 rows @kp0+4, sub3 rows+8 @kp0+4
    const int a_lrow  = (lane & 7) + ((lane >> 3) & 1) * 8;
    const int a_lpair = (lane >> 4) * 4;
    // B x4 (2 n-tiles): sub0 (nt0,kp0), sub1 (nt0,kp0+4), sub2 (nt1,kp0), sub3 (nt1,kp0+4)
    const int b_lrow  = (lane & 7) + (lane >> 4) * 8;
    const int b_lpair = ((lane >> 3) & 1) * 4;

    const uint32_t qhb_s = smem_u32(qhb), qlb_s = smem_u32(qlb);
    const uint32_t phb_s = smem_u32(phb), plb_s = smem_u32(plb);
    const uint32_t aoff = (uint32_t)(a_lrow * 36 + a_lpair) * 4u;
    const uint32_t boff = (uint32_t)(b_lrow * 36 + b_lpair) * 4u;
    const int nbase0 = wg_n * 32;

    #pragma unroll
    for (int ki = 0; ki < 4; ++ki) {
        const int kp0 = ki * 8;
        uint32_t bh0[4], bh1[4], bl0[4], bl1[4];
        #pragma unroll
        for (int nn = 0; nn < 2; ++nn) {
            uint32_t ba = (uint32_t)(((nbase0 + nn * 16) * 36 + kp0) * 4);
            ldsm_x4(bh0[2 * nn], bh1[2 * nn], bh0[2 * nn + 1], bh1[2 * nn + 1],
                    phb_s + ba + boff);
            ldsm_x4(bl0[2 * nn], bl1[2 * nn], bl0[2 * nn + 1], bl1[2 * nn + 1],
                    plb_s + ba + boff);
        }
        #pragma unroll
        for (int mt = 0; mt < 4; ++mt) {
            const int r0 = (wg_m * 4 + mt) * 16;
            uint32_t aa = (uint32_t)((r0 * 36 + kp0) * 4);
            uint32_t ah0, ah1, ah2, ah3, al0, al1, al2, al3;
            ldsm_x4(ah0, ah1, ah2, ah3, qhb_s + aa + aoff);
            ldsm_x4(al0, al1, al2, al3, qlb_s + aa + aoff);
            #pragma unroll
            for (int nt = 0; nt < 4; ++nt) {
                mma16b(acc[mt][nt], ah0, ah1, ah2, ah3, bh0[nt], bh1[nt]);
                mma16b(acc[mt][nt], ah0, ah1, ah2, ah3, bl0[nt], bl1[nt]);
                mma16b(acc[mt][nt], al0, al1, al2, al3, bh0[nt], bh1[nt]);
            }
        }
    }

    #pragma unroll
    for (int mt = 0; mt < 4; ++mt) {
        const int rA = (wg_m * 4 + mt) * 16 + tq, rB = rA + 8;
        float mA = -3.4e38f, mB = -3.4e38f;
        #pragma unroll
        for (int nt = 0; nt < 4; ++nt) {
            mA = fmaxf(mA, fmaxf(acc[mt][nt][0], acc[mt][nt][1]));
            mB = fmaxf(mB, fmaxf(acc[mt][nt][2], acc[mt][nt][3]));
        }
        mA = fmaxf(mA, __shfl_xor_sync(0xffffffffu, mA, 1));
        mA = fmaxf(mA, __shfl_xor_sync(0xffffffffu, mA, 2));
        mB = fmaxf(mB, __shfl_xor_sync(0xffffffffu, mB, 1));
        mB = fmaxf(mB, __shfl_xor_sync(0xffffffffu, mB, 2));
        if (tr == 0) {
            pmax[rA * 8 + wg_n] = mA;
            pmax[rB * 8 + wg_n] = mB;
        }
    }
    __syncthreads();

    if (tid < 128) {
        float m = pmax[tid * 8];
        #pragma unroll
        for (int w = 1; w < 8; ++w) m = fmaxf(m, pmax[tid * 8 + w]);
        rmax[tid] = m;
    }
    __syncthreads();

    if (!is_query && wid == 0) {
        float m = -3.4e38f;
        #pragma unroll
        for (int i = 0; i < 4; ++i) m = fmaxf(m, rmax[lane * 4 + i]);
        #pragma unroll
        for (int o = 16; o > 0; o >>= 1)
            m = fmaxf(m, __shfl_xor_sync(0xffffffffu, m, o));
        if (lane == 0) {
            unsigned u = __float_as_uint(m);
            u = (u & 0x80000000u) ? ~u : (u | 0x80000000u);
            atomicMax(&g_kmax[blockIdx.x >> 5], u);
        }
    }

    #pragma unroll
    for (int mt = 0; mt < 4; ++mt) {
        const int rA = (wg_m * 4 + mt) * 16 + tq, rB = rA + 8;
        float offA = DIAG_C * (dsum[2 * rA] + dsum[2 * rA + 1]);
        float offB = DIAG_C * (dsum[2 * rB] + dsum[2 * rB + 1]);
        if (is_query) { offA += rmax[rA]; offB += rmax[rB]; }
        float* oA = outg + (base + rA) * MFEAT + wg_n * 32;
        float* oB = outg + (base + rB) * MFEAT + wg_n * 32;
        #pragma unroll
        for (int nt = 0; nt < 4; ++nt) {
            int c0 = nt * 8 + 2 * tr;
            float v0, v1, v2, v3;
            if (is_query) {
                v0 = RATIO_F * (__expf(acc[mt][nt][0] - offA) + EPS_KF);
                v1 = RATIO_F * (__expf(acc[mt][nt][1] - offA) + EPS_KF);
                v2 = RATIO_F * (__expf(acc[mt][nt][2] - offB) + EPS_KF);
                v3 = RATIO_F * (__expf(acc[mt][nt][3] - offB) + EPS_KF);
            } else {
                v0 = __expf(acc[mt][nt][0] - offA);
                v1 = __expf(acc[mt][nt][1] - offA);
                v2 = __expf(acc[mt][nt][2] - offB);
                v3 = __expf(acc[mt][nt][3] - offB);
            }
            *reinterpret_cast<float2*>(oA + c0) = make_float2(v0, v1);
            *reinterpret_cast<float2*>(oB + c0) = make_float2(v2, v3);
        }
    }
}

// ---------------------------------------------------------------------------
// chunk sums via mma: 2 CTAs per chunk (m-halves), 256 threads, 2 CTAs/SM.
#define CKS 136
#define CK_VSO (128 * CKS)
#define CK_SMEMF (CK_VSO + 128 * 72)
__global__ void __launch_bounds__(256, 2)
chunk_mma_kernel(const float* __restrict__ vin) {
    extern __shared__ float sf[];
    float* ksm = sf;                 // [128 k][128 m-local]
    float* vsm = sf + CK_VSO;        // [128 k][72]

    const int tid = threadIdx.x;
    const int wid = tid >> 5, lane = tid & 31;
    const int tq = lane >> 2, tr = lane & 3;
    const int bix = blockIdx.x;
    const int cix = bix >> 1;
    const int mhalf = bix & 1;
    const size_t base_row = (size_t)(cix / NCH) * NSEQ + (size_t)(cix % NCH) * CHK;

    const float mx = decode_max(g_kmax[cix >> 5]);
    const float aK = RATIO_F * __expf(-mx);
    const float bK = RATIO_F * EPS_KF;

    {
        const float4* src = reinterpret_cast<const float4*>(g_phi_k + base_row * MFEAT);
        #pragma unroll
        for (int i = 0; i < 16; ++i) {
            int idx = tid + i * 256;
            int r = idx >> 5, c4 = idx & 31;
            float4 t = src[r * 64 + mhalf * 32 + c4];
            t.x = tf32r(fmaf(aK, t.x, bK)); t.y = tf32r(fmaf(aK, t.y, bK));
            t.z = tf32r(fmaf(aK, t.z, bK)); t.w = tf32r(fmaf(aK, t.w, bK));
            *reinterpret_cast<float4*>(ksm + r * CKS + 4 * c4) = t;
        }
    }
    {
        const float4* src = reinterpret_cast<const float4*>(vin + base_row * EDIM);
        #pragma unroll
        for (int i = 0; i < 8; ++i) {
            int idx = tid + i * 256;
            int r = idx >> 4, c4 = idx & 15;
            float4 t = src[idx];
            t.x = tf32r(t.x); t.y = tf32r(t.y); t.z = tf32r(t.z); t.w = tf32r(t.w);
            *reinterpret_cast<float4*>(vsm + r * 72 + 4 * c4) = t;
        }
        if (tid < 128) {
            *reinterpret_cast<float4*>(vsm + tid * 72 + 64) = make_float4(1.f, 0.f, 0.f, 0.f);
            *reinterpret_cast<float4*>(vsm + tid * 72 + 68) = make_float4(0.f, 0.f, 0.f, 0.f);
        }
    }
    __syncthreads();

    const int m0 = wid * 16;
    float acc[9][4];
    #pragma unroll
    for (int nt = 0; nt < 9; ++nt)
        #pragma unroll
        for (int i = 0; i < 4; ++i) acc[nt][i] = 0.f;

    #pragma unroll 4
    for (int ks = 0; ks < 16; ++ks) {
        const int k0 = ks * 8;
        uint32_t a0 = F2U(ksm[(k0 + tr) * CKS + m0 + tq]);
        uint32_t a1 = F2U(ksm[(k0 + tr) * CKS + m0 + tq + 8]);
        uint32_t a2 = F2U(ksm[(k0 + tr + 4) * CKS + m0 + tq]);
        uint32_t a3 = F2U(ksm[(k0 + tr + 4) * CKS + m0 + tq + 8]);
        #pragma unroll
        for (int nt = 0; nt < 9; ++nt) {
            uint32_t b0 = F2U(vsm[(k0 + tr) * 72 + nt * 8 + tq]);
            uint32_t b1 = F2U(vsm[(k0 + tr + 4) * 72 + nt * 8 + tq]);
            mma8(acc[nt], a0, a1, a2, a3, b0, b1);
        }
    }

    float* Sg = g_S + (size_t)cix * MFEAT * EDIM;
    float* zg = g_z + (size_t)cix * MFEAT;
    {
        int m = mhalf * 128 + m0 + tq;
        #pragma unroll
        for (int nt = 0; nt < 8; ++nt) {
            int c0 = nt * 8 + 2 * tr;
            *reinterpret_cast<float2*>(Sg + m * EDIM + c0)
                = make_float2(acc[nt][0], acc[nt][1]);
            *reinterpret_cast<float2*>(Sg + (m + 8) * EDIM + c0)
                = make_float2(acc[nt][2], acc[nt][3]);
        }
        if (tr == 0) {
            zg[m]     = acc[8][0];
            zg[m + 8] = acc[8][2];
        }
    }
}

// ---------------------------------------------------------------------------
__global__ void prefix_kernel() {
    const int idx = blockIdx.x * blockDim.x + threadIdx.x;
    const int T1 = BHC * MFEAT * EDIM;
    if (idx < T1) {
        int bh = idx / (MFEAT * EDIM);
        int rem = idx % (MFEAT * EDIM);
        size_t base = (size_t)bh * NCH * MFEAT * EDIM + rem;
        float run = 0.f;
        #pragma unroll
        for (int c = 0; c < NCH; ++c) {
            size_t p = base + (size_t)c * MFEAT * EDIM;
            float t = g_S[p]; g_S[p] = run; run += t;
        }
    } else if (idx < T1 + BHC * MFEAT) {
        int j = idx - T1;
        int bh = j / MFEAT;
        int rem = j % MFEAT;
        size_t base = (size_t)bh * NCH * MFEAT + rem;
        float run = 0.f;
        #pragma unroll
        for (int c = 0; c < NCH; ++c) {
            size_t p = base + (size_t)c * MFEAT;
            float t = g_z[p]; g_z[p] = run; run += t;
        }
    }
}

// ---------------------------------------------------------------------------
// out kernel (256 threads) with SMSP-balanced causal n-tile skip.
#define SA 140
#define SB 72
#define BUFA 0
#define BUFB (128 * SA)
#define BUFS (2 * 128 * SA)
#define ZSO  (BUFS + 128 * SB)
#define QZ2O (ZSO + 256)
#define SQ2O (QZ2O + 256)
#define SUMO (SQ2O + 256)
#define DENO (SUMO + 128)
#define OUT_SMEMF (DENO + 128)

__global__ void __launch_bounds__(256, 1)
out_mma_kernel(const float* __restrict__ vin, float* __restrict__ outp) {
    extern __shared__ float sf[];
    float* bufA = sf + BUFA;
    float* bufB = sf + BUFB;
    float* bufS = sf + BUFS;
    float* zs   = sf + ZSO;
    float* qz2  = sf + QZ2O;
    float* sq2  = sf + SQ2O;
    float* sums = sf + SUMO;
    float* den  = sf + DENO;

    const int tid = threadIdx.x;
    const int wid = tid >> 5, lane = tid & 31;
    const int tq = lane >> 2, tr = lane & 3;
    const int qr = lane >> 3, qc = lane & 7;
    const int cix = blockIdx.x;
    const size_t base_row = (size_t)(cix / NCH) * NSEQ + (size_t)(cix % NCH) * CHK;

    const int mt_t = (wid < 4) ? wid : 11 - wid;
    const int m0 = mt_t * 16;
    const int ngroups = (mt_t + 2) >> 1;

    const float mx = decode_max(g_kmax[cix >> 5]);
    const float aK = RATIO_F * __expf(-mx);
    const float bK = RATIO_F * EPS_KF;

    zs[tid] = g_z[(size_t)cix * MFEAT + tid];

    float sacc[16][4];
    float iacc[8][4];
    #pragma unroll
    for (int nt = 0; nt < 16; ++nt)
        #pragma unroll
        for (int i = 0; i < 4; ++i) sacc[nt][i] = 0.f;
    #pragma unroll
    for (int nt = 0; nt < 8; ++nt)
        #pragma unroll
        for (int i = 0; i < 4; ++i) iacc[nt][i] = 0.f;

    float qzr = 0.f, sqr = 0.f;
    const float4* gq4 = reinterpret_cast<const float4*>(g_phi_q + base_row * MFEAT);
    const float4* gk4 = reinterpret_cast<const float4*>(g_phi_k + base_row * MFEAT);

    for (int h = 0; h < 2; ++h) {
        __syncthreads();
        const float4* Sg4 = reinterpret_cast<const float4*>(
            g_S + (size_t)cix * MFEAT * EDIM + (size_t)h * 128 * EDIM);
        #pragma unroll
        for (int j = 0; j < 4; ++j) {
            int r = wid * 4 + qr + 32 * j;
            #pragma unroll
            for (int i = 0; i < 4; ++i) {
                int c4 = qc + 8 * i;
                float4 tA = gq4[r * 64 + h * 32 + c4];
                float4 tB = gk4[r * 64 + h * 32 + c4];
                tA.x = tf32r(tA.x); tA.y = tf32r(tA.y); tA.z = tf32r(tA.z); tA.w = tf32r(tA.w);
                tB.x = tf32r(fmaf(aK, tB.x, bK)); tB.y = tf32r(fmaf(aK, tB.y, bK));
                tB.z = tf32r(fmaf(aK, tB.z, bK)); tB.w = tf32r(fmaf(aK, tB.w, bK));
                *reinterpret_cast<float4*>(bufA + r * SA + 4 * c4) = tA;
                *reinterpret_cast<float4*>(bufB + r * SA + 4 * c4) = tB;
            }
            #pragma unroll
            for (int i = 0; i < 2; ++i) {
                int c4 = qc + 8 * i;
                float4 tS = Sg4[r * 16 + c4];
                tS.x = tf32r(tS.x); tS.y = tf32r(tS.y); tS.z = tf32r(tS.z); tS.w = tf32r(tS.w);
                *reinterpret_cast<float4*>(bufS + r * SB + 4 * c4) = tS;
            }
        }
        __syncthreads();

        #pragma unroll 2
        for (int ks = 0; ks < 16; ++ks) {
            const int k0 = ks * 8;
            uint32_t a0 = F2U(bufA[(m0 + tq) * SA + k0 + tr]);
            uint32_t a1 = F2U(bufA[(m0 + tq + 8) * SA + k0 + tr]);
            uint32_t a2 = F2U(bufA[(m0 + tq) * SA + k0 + tr + 4]);
            uint32_t a3 = F2U(bufA[(m0 + tq + 8) * SA + k0 + tr + 4]);
            #pragma unroll
            for (int g = 0; g < 4; ++g) {
                if (g < ngroups) {
                    #pragma unroll
                    for (int j = 0; j < 4; ++j) {
                        const int nt = g * 4 + j;
                        uint32_t b0 = F2U(bufB[(nt * 8 + tq) * SA + k0 + tr]);
                        uint32_t b1 = F2U(bufB[(nt * 8 + tq) * SA + k0 + tr + 4]);
                        mma8(sacc[nt], a0, a1, a2, a3, b0, b1);
                    }
                }
            }
            #pragma unroll
            for (int nt = 0; nt < 8; ++nt) {
                uint32_t b0 = F2U(bufS[(k0 + tr) * SB + nt * 8 + tq]);
                uint32_t b1 = F2U(bufS[(k0 + tr + 4) * SB + nt * 8 + tq]);
                mma8(iacc[nt], a0, a1, a2, a3, b0, b1);
            }
        }
        {
            const float* pq = bufA + (tid >> 1) * SA + (tid & 1) * 64;
            const float* pz = zs + h * 128 + (tid & 1) * 64;
            #pragma unroll 8
            for (int j = 0; j < 64; ++j) {
                qzr = fmaf(pq[j], pz[j], qzr);
                sqr += pq[j];
            }
        }
    }

    __syncthreads();

    const int rlo = m0 + tq, rhi = rlo + 8;
    {
        float rsl = 0.f, rsh = 0.f;
        #pragma unroll
        for (int nt = 0; nt < 16; ++nt) {
            int c0 = nt * 8 + 2 * tr;
            float s0 = (c0     <= rlo) ? sacc[nt][0] : 0.f;
            float s1 = (c0 + 1 <= rlo) ? sacc[nt][1] : 0.f;
            float s2 = (c0     <= rhi) ? sacc[nt][2] : 0.f;
            float s3 = (c0 + 1 <= rhi) ? sacc[nt][3] : 0.f;
            rsl += s0 + s1; rsh += s2 + s3;
            *reinterpret_cast<float2*>(bufA + rlo * SA + c0) = make_float2(tf32r(s0), tf32r(s1));
            *reinterpret_cast<float2*>(bufA + rhi * SA + c0) = make_float2(tf32r(s2), tf32r(s3));
        }
        rsl += __shfl_xor_sync(0xffffffffu, rsl, 1);
        rsl += __shfl_xor_sync(0xffffffffu, rsl, 2);
        rsh += __shfl_xor_sync(0xffffffffu, rsh, 1);
        rsh += __shfl_xor_sync(0xffffffffu, rsh, 2);
        if (tr == 0) { sums[rlo] = rsl; sums[rhi] = rsh; }
    }
    {
        const float4* vg4 = reinterpret_cast<const float4*>(vin + base_row * EDIM);
        #pragma unroll
        for (int j = 0; j < 4; ++j) {
            int r = wid * 4 + qr + 32 * j;
            #pragma unroll
            for (int i = 0; i < 2; ++i) {
                int c4 = qc + 8 * i;
                float4 t = vg4[r * 16 + c4];
                t.x = tf32r(t.x); t.y = tf32r(t.y); t.z = tf32r(t.z); t.w = tf32r(t.w);
                *reinterpret_cast<float4*>(bufB + r * SB + 4 * c4) = t;
            }
        }
    }
    qz2[tid] = qzr; sq2[tid] = sqr;
    __syncthreads();

    if (tid < 128) {
        float d = qz2[2 * tid] + qz2[2 * tid + 1] + sums[tid]
                + EPS_DF * (sq2[2 * tid] + sq2[2 * tid + 1]);
        den[tid] = 1.f / d;
    }

    #pragma unroll 2
    for (int ks = 0; ks < 16; ++ks) {
        const int k0 = ks * 8;
        uint32_t a0 = F2U(bufA[(m0 + tq) * SA + k0 + tr]);
        uint32_t a1 = F2U(bufA[(m0 + tq + 8) * SA + k0 + tr]);
        uint32_t a2 = F2U(bufA[(m0 + tq) * SA + k0 + tr + 4]);
        uint32_t a3 = F2U(bufA[(m0 + tq + 8) * SA + k0 + tr + 4]);
        #pragma unroll
        for (int nt = 0; nt < 8; ++nt) {
            uint32_t b0 = F2U(bufB[(k0 + tr) * SB + nt * 8 + tq]);
            uint32_t b1 = F2U(bufB[(k0 + tr + 4) * SB + nt * 8 + tq]);
            mma8(iacc[nt], a0, a1, a2, a3, b0, b1);
        }
    }
    __syncthreads();

    {
        float il = den[rlo], ih = den[rhi];
        float* olo = outp + (base_row + rlo) * EDIM;
        float* ohi = outp + (base_row + rhi) * EDIM;
        #pragma unroll
        for (int nt = 0; nt < 8; ++nt) {
            int c0 = nt * 8 + 2 * tr;
            *reinterpret_cast<float2*>(olo + c0) = make_float2(iacc[nt][0] * il, iacc[nt][1] * il);
            *reinterpret_cast<float2*>(ohi + c0) = make_float2(iacc[nt][2] * ih, iacc[nt][3] * ih);
        }
    }
}

// ---------------------------------------------------------------------------
extern "C" void kernel_launch(void* const* d_in, const int* in_sizes, int n_in,
                              void* d_out, int out_size) {
    const float* big[3] = {nullptr, nullptr, nullptr};
    const float* proj = nullptr;
    int nb = 0;
    for (int i = 0; i < n_in; ++i) {
        if (in_sizes[i] == MFEAT * DDIM) proj = (const float*)d_in[i];
        else if (nb < 3) big[nb++] = (const float*)d_in[i];
    }
    const float* q = big[0];
    const float* k = big[1];
    const float* v = big[2];
    float* out = (float*)d_out;

    cudaFuncSetAttribute(phi_mma_kernel, cudaFuncAttributeMaxDynamicSharedMemorySize,
                         PHI_SMEMW * 4);
    cudaFuncSetAttribute(chunk_mma_kernel, cudaFuncAttributeMaxDynamicSharedMemorySize,
                         CK_SMEMF * (int)sizeof(float));
    cudaFuncSetAttribute(out_mma_kernel, cudaFuncAttributeMaxDynamicSharedMemorySize,
                         OUT_SMEMF * (int)sizeof(float));

    init_kmax_kernel<<<1, 32>>>();
    proj_prep_kernel<<<32, 256>>>(proj);
    phi_mma_kernel<<<BHC * NSEQ / 128, 512, PHI_SMEMW * 4>>>(q, 1);
    phi_mma_kernel<<<BHC * NSEQ / 128, 512, PHI_SMEMW * 4>>>(k, 0);
    chunk_mma_kernel<<<BHC * NCH * 2, 256, CK_SMEMF * sizeof(float)>>>(v);
    prefix_kernel<<<(BHC * MFEAT * EDIM + BHC * MFEAT) / 256, 256>>>();
    out_mma_kernel<<<BHC * NCH, 256, OUT_SMEMF * sizeof(float)>>>(v, out);
}

// round 17
// speedup vs baseline: 1.3563x; 1.0651x over previous
#include <cuda_runtime.h>
#include <cuda_bf16.h>
#include <cstdint>
#include <math.h>

// Problem constants
#define BHC   16
#define NSEQ  4096
#define DDIM  64
#define MFEAT 256
#define EDIM  64
#define CHK   128
#define NCH   32

#define NORM_F   0.35355339059327373f
#define DIAG_C   0.0625f
#define RATIO_F  0.0625f
#define EPS_KF   1e-4f
#define EPS_DF   1e-6f

// Scratch (static device globals)
__device__ float    g_phi_q[BHC * NSEQ * MFEAT];   // 64 MiB
__device__ float    g_phi_k[BHC * NSEQ * MFEAT];   // 64 MiB (E = exp(dd - diag))
__device__ float    g_S[BHC * NCH * MFEAT * EDIM]; // 32 MiB
__device__ float    g_z[BHC * NCH * MFEAT];
__device__ unsigned g_kmax[BHC];
__device__ uint32_t g_pjh[MFEAT * DDIM / 2];       // packed bf16-hi pairs
__device__ uint32_t g_pjl[MFEAT * DDIM / 2];       // packed bf16-lo pairs

// ---------------------------------------------------------------------------
__device__ __forceinline__ float tf32r(float x) {
    uint32_t u;
    asm("cvt.rna.tf32.f32 %0, %1;" : "=r"(u) : "f"(x));
    return __uint_as_float(u);
}
#define F2U(x) __float_as_uint(x)

__device__ __forceinline__ uint32_t smem_u32(const void* p) {
    return (uint32_t)__cvta_generic_to_shared(p);
}

__device__ __forceinline__ void ldsm_x4(uint32_t& d0, uint32_t& d1,
                                        uint32_t& d2, uint32_t& d3, uint32_t addr) {
    asm volatile("ldmatrix.sync.aligned.m8n8.x4.shared.b16 {%0,%1,%2,%3}, [%4];"
                 : "=r"(d0), "=r"(d1), "=r"(d2), "=r"(d3) : "r"(addr));
}

__device__ __forceinline__ void mma8(float* c, uint32_t a0, uint32_t a1,
                                     uint32_t a2, uint32_t a3,
                                     uint32_t b0, uint32_t b1) {
    asm volatile("mma.sync.aligned.m16n8k8.row.col.f32.tf32.tf32.f32 "
                 "{%0,%1,%2,%3},{%4,%5,%6,%7},{%8,%9},{%0,%1,%2,%3};"
                 : "+f"(c[0]), "+f"(c[1]), "+f"(c[2]), "+f"(c[3])
                 : "r"(a0), "r"(a1), "r"(a2), "r"(a3), "r"(b0), "r"(b1));
}

__device__ __forceinline__ void mma16b(float* c, uint32_t a0, uint32_t a1,
                                       uint32_t a2, uint32_t a3,
                                       uint32_t b0, uint32_t b1) {
    asm volatile("mma.sync.aligned.m16n8k16.row.col.f32.bf16.bf16.f32 "
                 "{%0,%1,%2,%3},{%4,%5,%6,%7},{%8,%9},{%0,%1,%2,%3};"
                 : "+f"(c[0]), "+f"(c[1]), "+f"(c[2]), "+f"(c[3])
                 : "r"(a0), "r"(a1), "r"(a2), "r"(a3), "r"(b0), "r"(b1));
}

__device__ __forceinline__ float decode_max(unsigned u) {
    return __uint_as_float((u & 0x80000000u) ? (u ^ 0x80000000u) : ~u);
}

__device__ __forceinline__ void split_pack(float a, float b, uint32_t& hi, uint32_t& lo) {
    __nv_bfloat16 ha = __float2bfloat16_rn(a);
    __nv_bfloat16 hb = __float2bfloat16_rn(b);
    __nv_bfloat16 la = __float2bfloat16_rn(a - __bfloat162float(ha));
    __nv_bfloat16 lb = __float2bfloat16_rn(b - __bfloat162float(hb));
    __nv_bfloat162 hv = __halves2bfloat162(ha, hb);
    __nv_bfloat162 lv = __halves2bfloat162(la, lb);
    hi = *reinterpret_cast<uint32_t*>(&hv);
    lo = *reinterpret_cast<uint32_t*>(&lv);
}

// ---------------------------------------------------------------------------
// prep: split NORM*proj into packed bf16 hi/lo pairs; also zero g_kmax
__global__ void proj_prep_kernel(const float* __restrict__ proj) {
    int idx = blockIdx.x * blockDim.x + threadIdx.x;   // pair index
    if (idx < BHC) g_kmax[idx] = 0u;
    if (idx < MFEAT * DDIM / 2) {
        float a = proj[2 * idx] * NORM_F;
        float b = proj[2 * idx + 1] * NORM_F;
        uint32_t h, l;
        split_pack(a, b, h, l);
        g_pjh[idx] = h;
        g_pjl[idx] = l;
    }
}

// ---------------------------------------------------------------------------
// fused phi (q + k passes in one launch): blocks [0,512) -> q, [512,1024) -> k
#define PH_QH  0
#define PH_QL  4608
#define PH_PHB 9216
#define PH_PLB 18432
#define PH_PMAX 27648           // [128][8]
#define PH_DSUM 28672           // [256]
#define PH_RMAX 28928           // [128]
#define PHI_SMEMW 29056

__global__ void __launch_bounds__(512, 1)
phi_mma_kernel(const float* __restrict__ qin, const float* __restrict__ kin) {
    extern __shared__ uint32_t su[];
    uint32_t* qhb = su + PH_QH;       // [128][36] packed bf16 pairs
    uint32_t* qlb = su + PH_QL;
    uint32_t* phb = su + PH_PHB;      // [256][36]
    uint32_t* plb = su + PH_PLB;
    float* pmax = reinterpret_cast<float*>(su + PH_PMAX);
    float* dsum = reinterpret_cast<float*>(su + PH_DSUM);
    float* rmax = reinterpret_cast<float*>(su + PH_RMAX);

    const int tid = threadIdx.x;
    const int wid = tid >> 5, lane = tid & 31;
    const int tq = lane >> 2, tr = lane & 3;
    const int wg_n = wid & 7, wg_m = wid >> 3;
    const int is_query = (blockIdx.x < 512) ? 1 : 0;
    const int bix = blockIdx.x & 511;
    const float* data = is_query ? qin : kin;
    const size_t base = (size_t)bix * 128;
    float* outg = is_query ? g_phi_q : g_phi_k;

    {
        const float4* src = reinterpret_cast<const float4*>(data + base * DDIM);
        #pragma unroll
        for (int i = 0; i < 4; ++i) {
            int idx = tid + i * 512;
            int r = idx >> 4, c4 = idx & 15;
            float4 t = src[idx];
            uint32_t h0, l0, h1, l1;
            split_pack(t.x, t.y, h0, l0);
            split_pack(t.z, t.w, h1, l1);
            *reinterpret_cast<uint2*>(qhb + r * 36 + 2 * c4) = make_uint2(h0, h1);
            *reinterpret_cast<uint2*>(qlb + r * 36 + 2 * c4) = make_uint2(l0, l1);
        }
    }
    {
        const uint4* sh = reinterpret_cast<const uint4*>(g_pjh);
        const uint4* sl = reinterpret_cast<const uint4*>(g_pjl);
        #pragma unroll
        for (int i = 0; i < 4; ++i) {
            int idx = tid + i * 512;
            int r = idx >> 3, k4 = idx & 7;
            *reinterpret_cast<uint4*>(phb + r * 36 + 4 * k4) = sh[idx];
            *reinterpret_cast<uint4*>(plb + r * 36 + 4 * k4) = sl[idx];
        }
    }
    __syncthreads();

    if (tid < 256) {
        int r = tid >> 1, hf = tid & 1;
        float s = 0.f;
        #pragma unroll 8
        for (int c = 0; c < 16; ++c) {
            uint32_t hu = qhb[r * 36 + hf * 16 + c];
            uint32_t lu = qlb[r * 36 + hf * 16 + c];
            float2 h = __bfloat1622float2(*reinterpret_cast<__nv_bfloat162*>(&hu));
            float2 l = __bfloat1622float2(*reinterpret_cast<__nv_bfloat162*>(&lu));
            float x0 = h.x + l.x, x1 = h.y + l.y;
            s = fmaf(x0, x0, fmaf(x1, x1, s));
        }
        dsum[tid] = s;
    }

    float acc[4][4][4];
    #pragma unroll
    for (int mt = 0; mt < 4; ++mt)
        #pragma unroll
        for (int nt = 0; nt < 4; ++nt)
            #pragma unroll
            for (int i = 0; i < 4; ++i) acc[mt][nt][i] = 0.f;

    const int a_lrow  = (lane & 7) + ((lane >> 3) & 1) * 8;
    const int a_lpair = (lane >> 4) * 4;
    const int b_lrow  = (lane & 7) + (lane >> 4) * 8;
    const int b_lpair = ((lane >> 3) & 1) * 4;

    const uint32_t qhb_s = smem_u32(qhb), qlb_s = smem_u32(qlb);
    const uint32_t phb_s = smem_u32(phb), plb_s = smem_u32(plb);
    const uint32_t aoff = (uint32_t)(a_lrow * 36 + a_lpair) * 4u;
    const uint32_t boff = (uint32_t)(b_lrow * 36 + b_lpair) * 4u;
    const int nbase0 = wg_n * 32;

    #pragma unroll
    for (int ki = 0; ki < 4; ++ki) {
        const int kp0 = ki * 8;
        uint32_t bh0[4], bh1[4], bl0[4], bl1[4];
        #pragma unroll
        for (int nn = 0; nn < 2; ++nn) {
            uint32_t ba = (uint32_t)(((nbase0 + nn * 16) * 36 + kp0) * 4);
            ldsm_x4(bh0[2 * nn], bh1[2 * nn], bh0[2 * nn + 1], bh1[2 * nn + 1],
                    phb_s + ba + boff);
            ldsm_x4(bl0[2 * nn], bl1[2 * nn], bl0[2 * nn + 1], bl1[2 * nn + 1],
                    plb_s + ba + boff);
        }
        #pragma unroll
        for (int mt = 0; mt < 4; ++mt) {
            const int r0 = (wg_m * 4 + mt) * 16;
            uint32_t aa = (uint32_t)((r0 * 36 + kp0) * 4);
            uint32_t ah0, ah1, ah2, ah3, al0, al1, al2, al3;
            ldsm_x4(ah0, ah1, ah2, ah3, qhb_s + aa + aoff);
            ldsm_x4(al0, al1, al2, al3, qlb_s + aa + aoff);
            #pragma unroll
            for (int nt = 0; nt < 4; ++nt) {
                mma16b(acc[mt][nt], ah0, ah1, ah2, ah3, bh0[nt], bh1[nt]);
                mma16b(acc[mt][nt], ah0, ah1, ah2, ah3, bl0[nt], bl1[nt]);
                mma16b(acc[mt][nt], al0, al1, al2, al3, bh0[nt], bh1[nt]);
            }
        }
    }

    #pragma unroll
    for (int mt = 0; mt < 4; ++mt) {
        const int rA = (wg_m * 4 + mt) * 16 + tq, rB = rA + 8;
        float mA = -3.4e38f, mB = -3.4e38f;
        #pragma unroll
        for (int nt = 0; nt < 4; ++nt) {
            mA = fmaxf(mA, fmaxf(acc[mt][nt][0], acc[mt][nt][1]));
            mB = fmaxf(mB, fmaxf(acc[mt][nt][2], acc[mt][nt][3]));
        }
        mA = fmaxf(mA, __shfl_xor_sync(0xffffffffu, mA, 1));
        mA = fmaxf(mA, __shfl_xor_sync(0xffffffffu, mA, 2));
        mB = fmaxf(mB, __shfl_xor_sync(0xffffffffu, mB, 1));
        mB = fmaxf(mB, __shfl_xor_sync(0xffffffffu, mB, 2));
        if (tr == 0) {
            pmax[rA * 8 + wg_n] = mA;
            pmax[rB * 8 + wg_n] = mB;
        }
    }
    __syncthreads();

    if (tid < 128) {
        float m = pmax[tid * 8];
        #pragma unroll
        for (int w = 1; w < 8; ++w) m = fmaxf(m, pmax[tid * 8 + w]);
        rmax[tid] = m;
    }
    __syncthreads();

    if (!is_query && wid == 0) {
        float m = -3.4e38f;
        #pragma unroll
        for (int i = 0; i < 4; ++i) m = fmaxf(m, rmax[lane * 4 + i]);
        #pragma unroll
        for (int o = 16; o > 0; o >>= 1)
            m = fmaxf(m, __shfl_xor_sync(0xffffffffu, m, o));
        if (lane == 0) {
            unsigned u = __float_as_uint(m);
            u = (u & 0x80000000u) ? ~u : (u | 0x80000000u);
            atomicMax(&g_kmax[bix >> 5], u);
        }
    }

    #pragma unroll
    for (int mt = 0; mt < 4; ++mt) {
        const int rA = (wg_m * 4 + mt) * 16 + tq, rB = rA + 8;
        float offA = DIAG_C * (dsum[2 * rA] + dsum[2 * rA + 1]);
        float offB = DIAG_C * (dsum[2 * rB] + dsum[2 * rB + 1]);
        if (is_query) { offA += rmax[rA]; offB += rmax[rB]; }
        float* oA = outg + (base + rA) * MFEAT + wg_n * 32;
        float* oB = outg + (base + rB) * MFEAT + wg_n * 32;
        #pragma unroll
        for (int nt = 0; nt < 4; ++nt) {
            int c0 = nt * 8 + 2 * tr;
            float v0, v1, v2, v3;
            if (is_query) {
                v0 = RATIO_F * (__expf(acc[mt][nt][0] - offA) + EPS_KF);
                v1 = RATIO_F * (__expf(acc[mt][nt][1] - offA) + EPS_KF);
                v2 = RATIO_F * (__expf(acc[mt][nt][2] - offB) + EPS_KF);
                v3 = RATIO_F * (__expf(acc[mt][nt][3] - offB) + EPS_KF);
            } else {
                v0 = __expf(acc[mt][nt][0] - offA);
                v1 = __expf(acc[mt][nt][1] - offA);
                v2 = __expf(acc[mt][nt][2] - offB);
                v3 = __expf(acc[mt][nt][3] - offB);
            }
            *reinterpret_cast<float2*>(oA + c0) = make_float2(v0, v1);
            *reinterpret_cast<float2*>(oB + c0) = make_float2(v2, v3);
        }
    }
}

// ---------------------------------------------------------------------------
// chunk sums via mma: 2 CTAs per chunk (m-halves), 256 threads, 2 CTAs/SM.
#define CKS 136
#define CK_VSO (128 * CKS)
#define CK_SMEMF (CK_VSO + 128 * 72)
__global__ void __launch_bounds__(256, 2)
chunk_mma_kernel(const float* __restrict__ vin) {
    extern __shared__ float sf[];
    float* ksm = sf;                 // [128 k][128 m-local]
    float* vsm = sf + CK_VSO;        // [128 k][72]

    const int tid = threadIdx.x;
    const int wid = tid >> 5, lane = tid & 31;
    const int tq = lane >> 2, tr = lane & 3;
    const int bix = blockIdx.x;
    const int cix = bix >> 1;
    const int mhalf = bix & 1;
    const size_t base_row = (size_t)(cix / NCH) * NSEQ + (size_t)(cix % NCH) * CHK;

    const float mx = decode_max(g_kmax[cix >> 5]);
    const float aK = RATIO_F * __expf(-mx);
    const float bK = RATIO_F * EPS_KF;

    {
        const float4* src = reinterpret_cast<const float4*>(g_phi_k + base_row * MFEAT);
        #pragma unroll
        for (int i = 0; i < 16; ++i) {
            int idx = tid + i * 256;
            int r = idx >> 5, c4 = idx & 31;
            float4 t = src[r * 64 + mhalf * 32 + c4];
            t.x = tf32r(fmaf(aK, t.x, bK)); t.y = tf32r(fmaf(aK, t.y, bK));
            t.z = tf32r(fmaf(aK, t.z, bK)); t.w = tf32r(fmaf(aK, t.w, bK));
            *reinterpret_cast<float4*>(ksm + r * CKS + 4 * c4) = t;
        }
    }
    {
        const float4* src = reinterpret_cast<const float4*>(vin + base_row * EDIM);
        #pragma unroll
        for (int i = 0; i < 8; ++i) {
            int idx = tid + i * 256;
            int r = idx >> 4, c4 = idx & 15;
            float4 t = src[idx];
            t.x = tf32r(t.x); t.y = tf32r(t.y); t.z = tf32r(t.z); t.w = tf32r(t.w);
            *reinterpret_cast<float4*>(vsm + r * 72 + 4 * c4) = t;
        }
        if (tid < 128) {
            *reinterpret_cast<float4*>(vsm + tid * 72 + 64) = make_float4(1.f, 0.f, 0.f, 0.f);
            *reinterpret_cast<float4*>(vsm + tid * 72 + 68) = make_float4(0.f, 0.f, 0.f, 0.f);
        }
    }
    __syncthreads();

    const int m0 = wid * 16;
    float acc[9][4];
    #pragma unroll
    for (int nt = 0; nt < 9; ++nt)
        #pragma unroll
        for (int i = 0; i < 4; ++i) acc[nt][i] = 0.f;

    #pragma unroll 4
    for (int ks = 0; ks < 16; ++ks) {
        const int k0 = ks * 8;
        uint32_t a0 = F2U(ksm[(k0 + tr) * CKS + m0 + tq]);
        uint32_t a1 = F2U(ksm[(k0 + tr) * CKS + m0 + tq + 8]);
        uint32_t a2 = F2U(ksm[(k0 + tr + 4) * CKS + m0 + tq]);
        uint32_t a3 = F2U(ksm[(k0 + tr + 4) * CKS + m0 + tq + 8]);
        #pragma unroll
        for (int nt = 0; nt < 9; ++nt) {
            uint32_t b0 = F2U(vsm[(k0 + tr) * 72 + nt * 8 + tq]);
            uint32_t b1 = F2U(vsm[(k0 + tr + 4) * 72 + nt * 8 + tq]);
            mma8(acc[nt], a0, a1, a2, a3, b0, b1);
        }
    }

    float* Sg = g_S + (size_t)cix * MFEAT * EDIM;
    float* zg = g_z + (size_t)cix * MFEAT;
    {
        int m = mhalf * 128 + m0 + tq;
        #pragma unroll
        for (int nt = 0; nt < 8; ++nt) {
            int c0 = nt * 8 + 2 * tr;
            *reinterpret_cast<float2*>(Sg + m * EDIM + c0)
                = make_float2(acc[nt][0], acc[nt][1]);
            *reinterpret_cast<float2*>(Sg + (m + 8) * EDIM + c0)
                = make_float2(acc[nt][2], acc[nt][3]);
        }
        if (tr == 0) {
            zg[m]     = acc[8][0];
            zg[m + 8] = acc[8][2];
        }
    }
}

// ---------------------------------------------------------------------------
__global__ void prefix_kernel() {
    const int idx = blockIdx.x * blockDim.x + threadIdx.x;
    const int T1 = BHC * MFEAT * EDIM;
    if (idx < T1) {
        int bh = idx / (MFEAT * EDIM);
        int rem = idx % (MFEAT * EDIM);
        size_t base = (size_t)bh * NCH * MFEAT * EDIM + rem;
        float run = 0.f;
        #pragma unroll
        for (int c = 0; c < NCH; ++c) {
            size_t p = base + (size_t)c * MFEAT * EDIM;
            float t = g_S[p]; g_S[p] = run; run += t;
        }
    } else if (idx < T1 + BHC * MFEAT) {
        int j = idx - T1;
        int bh = j / MFEAT;
        int rem = j % MFEAT;
        size_t base = (size_t)bh * NCH * MFEAT + rem;
        float run = 0.f;
        #pragma unroll
        for (int c = 0; c < NCH; ++c) {
            size_t p = base + (size_t)c * MFEAT;
            float t = g_z[p]; g_z[p] = run; run += t;
        }
    }
}

// ---------------------------------------------------------------------------
// out kernel (256 threads), causal skip + z/1 ones-columns in the S tile
// (inter GEMM's 9th n-tile yields qz and sq in tensor ops).
#define SA 140
#define SB 72
#define BUFA 0
#define BUFB (128 * SA)
#define BUFS (2 * 128 * SA)
#define SUMO (BUFS + 128 * SB)
#define DENO (SUMO + 128)
#define OUT_SMEMF (DENO + 128)

__global__ void __launch_bounds__(256, 1)
out_mma_kernel(const float* __restrict__ vin, float* __restrict__ outp) {
    extern __shared__ float sf[];
    float* bufA = sf + BUFA;
    float* bufB = sf + BUFB;
    float* bufS = sf + BUFS;
    float* sums = sf + SUMO;
    float* den  = sf + DENO;

    const int tid = threadIdx.x;
    const int wid = tid >> 5, lane = tid & 31;
    const int tq = lane >> 2, tr = lane & 3;
    const int qr = lane >> 3, qc = lane & 7;
    const int cix = blockIdx.x;
    const size_t base_row = (size_t)(cix / NCH) * NSEQ + (size_t)(cix % NCH) * CHK;

    const int mt_t = (wid < 4) ? wid : 11 - wid;
    const int m0 = mt_t * 16;
    const int ngroups = (mt_t + 2) >> 1;

    const float mx = decode_max(g_kmax[cix >> 5]);
    const float aK = RATIO_F * __expf(-mx);
    const float bK = RATIO_F * EPS_KF;

    float sacc[16][4];
    float iacc[9][4];
    #pragma unroll
    for (int nt = 0; nt < 16; ++nt)
        #pragma unroll
        for (int i = 0; i < 4; ++i) sacc[nt][i] = 0.f;
    #pragma unroll
    for (int nt = 0; nt < 9; ++nt)
        #pragma unroll
        for (int i = 0; i < 4; ++i) iacc[nt][i] = 0.f;

    const float4* gq4 = reinterpret_cast<const float4*>(g_phi_q + base_row * MFEAT);
    const float4* gk4 = reinterpret_cast<const float4*>(g_phi_k + base_row * MFEAT);
    const float* zg = g_z + (size_t)cix * MFEAT;

    for (int h = 0; h < 2; ++h) {
        __syncthreads();
        const float4* Sg4 = reinterpret_cast<const float4*>(
            g_S + (size_t)cix * MFEAT * EDIM + (size_t)h * 128 * EDIM);
        #pragma unroll
        for (int j = 0; j < 4; ++j) {
            int r = wid * 4 + qr + 32 * j;
            #pragma unroll
            for (int i = 0; i < 4; ++i) {
                int c4 = qc + 8 * i;
                float4 tA = gq4[r * 64 + h * 32 + c4];
                float4 tB = gk4[r * 64 + h * 32 + c4];
                tA.x = tf32r(tA.x); tA.y = tf32r(tA.y); tA.z = tf32r(tA.z); tA.w = tf32r(tA.w);
                tB.x = tf32r(fmaf(aK, tB.x, bK)); tB.y = tf32r(fmaf(aK, tB.y, bK));
                tB.z = tf32r(fmaf(aK, tB.z, bK)); tB.w = tf32r(fmaf(aK, tB.w, bK));
                *reinterpret_cast<float4*>(bufA + r * SA + 4 * c4) = tA;
                *reinterpret_cast<float4*>(bufB + r * SA + 4 * c4) = tB;
            }
            #pragma unroll
            for (int i = 0; i < 2; ++i) {
                int c4 = qc + 8 * i;
                float4 tS = Sg4[r * 16 + c4];
                tS.x = tf32r(tS.x); tS.y = tf32r(tS.y); tS.z = tf32r(tS.z); tS.w = tf32r(tS.w);
                *reinterpret_cast<float4*>(bufS + r * SB + 4 * c4) = tS;
            }
        }
        // ones-column augmentation: col 64 = z_prev (this m-half), col 65 = 1
        if (tid < 128) {
            float zv = tf32r(zg[h * 128 + tid]);
            *reinterpret_cast<float4*>(bufS + tid * SB + 64) = make_float4(zv, 1.f, 0.f, 0.f);
            *reinterpret_cast<float4*>(bufS + tid * SB + 68) = make_float4(0.f, 0.f, 0.f, 0.f);
        }
        __syncthreads();

        #pragma unroll 2
        for (int ks = 0; ks < 16; ++ks) {
            const int k0 = ks * 8;
            uint32_t a0 = F2U(bufA[(m0 + tq) * SA + k0 + tr]);
            uint32_t a1 = F2U(bufA[(m0 + tq + 8) * SA + k0 + tr]);
            uint32_t a2 = F2U(bufA[(m0 + tq) * SA + k0 + tr + 4]);
            uint32_t a3 = F2U(bufA[(m0 + tq + 8) * SA + k0 + tr + 4]);
            #pragma unroll
            for (int g = 0; g < 4; ++g) {
                if (g < ngroups) {
                    #pragma unroll
                    for (int j = 0; j < 4; ++j) {
                        const int nt = g * 4 + j;
                        uint32_t b0 = F2U(bufB[(nt * 8 + tq) * SA + k0 + tr]);
                        uint32_t b1 = F2U(bufB[(nt * 8 + tq) * SA + k0 + tr + 4]);
                        mma8(sacc[nt], a0, a1, a2, a3, b0, b1);
                    }
                }
            }
            #pragma unroll
            for (int nt = 0; nt < 9; ++nt) {
                uint32_t b0 = F2U(bufS[(k0 + tr) * SB + nt * 8 + tq]);
                uint32_t b1 = F2U(bufS[(k0 + tr + 4) * SB + nt * 8 + tq]);
                mma8(iacc[nt], a0, a1, a2, a3, b0, b1);
            }
        }
    }

    __syncthreads();

    const int rlo = m0 + tq, rhi = rlo + 8;
    {
        float rsl = 0.f, rsh = 0.f;
        #pragma unroll
        for (int nt = 0; nt < 16; ++nt) {
            int c0 = nt * 8 + 2 * tr;
            float s0 = (c0     <= rlo) ? sacc[nt][0] : 0.f;
            float s1 = (c0 + 1 <= rlo) ? sacc[nt][1] : 0.f;
            float s2 = (c0     <= rhi) ? sacc[nt][2] : 0.f;
            float s3 = (c0 + 1 <= rhi) ? sacc[nt][3] : 0.f;
            rsl += s0 + s1; rsh += s2 + s3;
            *reinterpret_cast<float2*>(bufA + rlo * SA + c0) = make_float2(tf32r(s0), tf32r(s1));
            *reinterpret_cast<float2*>(bufA + rhi * SA + c0) = make_float2(tf32r(s2), tf32r(s3));
        }
        rsl += __shfl_xor_sync(0xffffffffu, rsl, 1);
        rsl += __shfl_xor_sync(0xffffffffu, rsl, 2);
        rsh += __shfl_xor_sync(0xffffffffu, rsh, 1);
        rsh += __shfl_xor_sync(0xffffffffu, rsh, 2);
        if (tr == 0) { sums[rlo] = rsl; sums[rhi] = rsh; }
    }
    // stage v (cols 0-63) + zero augmented cols 64-71 (so intra 9th tile adds 0)
    {
        const float4* vg4 = reinterpret_cast<const float4*>(vin + base_row * EDIM);
        #pragma unroll
        for (int j = 0; j < 4; ++j) {
            int r = wid * 4 + qr + 32 * j;
            #pragma unroll
            for (int i = 0; i < 2; ++i) {
                int c4 = qc + 8 * i;
                float4 t = vg4[r * 16 + c4];
                t.x = tf32r(t.x); t.y = tf32r(t.y); t.z = tf32r(t.z); t.w = tf32r(t.w);
                *reinterpret_cast<float4*>(bufB + r * SB + 4 * c4) = t;
            }
        }
        if (tid < 128) {
            *reinterpret_cast<float4*>(bufB + tid * SB + 64) = make_float4(0.f, 0.f, 0.f, 0.f);
            *reinterpret_cast<float4*>(bufB + tid * SB + 68) = make_float4(0.f, 0.f, 0.f, 0.f);
        }
    }
    __syncthreads();

    // den from the ones-column results: iacc[8] = (qz, sq) at tr==0
    if (tr == 0) {
        den[rlo] = 1.f / (iacc[8][0] + sums[rlo] + EPS_DF * iacc[8][1]);
        den[rhi] = 1.f / (iacc[8][2] + sums[rhi] + EPS_DF * iacc[8][3]);
    }

    // intra: iacc += masked_scores @ v (9th tile accumulates zeros)
    #pragma unroll 2
    for (int ks = 0; ks < 16; ++ks) {
        const int k0 = ks * 8;
        uint32_t a0 = F2U(bufA[(m0 + tq) * SA + k0 + tr]);
        uint32_t a1 = F2U(bufA[(m0 + tq + 8) * SA + k0 + tr]);
        uint32_t a2 = F2U(bufA[(m0 + tq) * SA + k0 + tr + 4]);
        uint32_t a3 = F2U(bufA[(m0 + tq + 8) * SA + k0 + tr + 4]);
        #pragma unroll
        for (int nt = 0; nt < 8; ++nt) {
            uint32_t b0 = F2U(bufB[(k0 + tr) * SB + nt * 8 + tq]);
            uint32_t b1 = F2U(bufB[(k0 + tr + 4) * SB + nt * 8 + tq]);
            mma8(iacc[nt], a0, a1, a2, a3, b0, b1);
        }
    }
    __syncthreads();

    {
        float il = den[rlo], ih = den[rhi];
        float* olo = outp + (base_row + rlo) * EDIM;
        float* ohi = outp + (base_row + rhi) * EDIM;
        #pragma unroll
        for (int nt = 0; nt < 8; ++nt) {
            int c0 = nt * 8 + 2 * tr;
            *reinterpret_cast<float2*>(olo + c0) = make_float2(iacc[nt][0] * il, iacc[nt][1] * il);
            *reinterpret_cast<float2*>(ohi + c0) = make_float2(iacc[nt][2] * ih, iacc[nt][3] * ih);
        }
    }
}

// ---------------------------------------------------------------------------
extern "C" void kernel_launch(void* const* d_in, const int* in_sizes, int n_in,
                              void* d_out, int out_size) {
    const float* big[3] = {nullptr, nullptr, nullptr};
    const float* proj = nullptr;
    int nb = 0;
    for (int i = 0; i < n_in; ++i) {
        if (in_sizes[i] == MFEAT * DDIM) proj = (const float*)d_in[i];
        else if (nb < 3) big[nb++] = (const float*)d_in[i];
    }
    const float* q = big[0];
    const float* k = big[1];
    const float* v = big[2];
    float* out = (float*)d_out;

    cudaFuncSetAttribute(phi_mma_kernel, cudaFuncAttributeMaxDynamicSharedMemorySize,
                         PHI_SMEMW * 4);
    cudaFuncSetAttribute(chunk_mma_kernel, cudaFuncAttributeMaxDynamicSharedMemorySize,
                         CK_SMEMF * (int)sizeof(float));
    cudaFuncSetAttribute(out_mma_kernel, cudaFuncAttributeMaxDynamicSharedMemorySize,
                         OUT_SMEMF * (int)sizeof(float));

    proj_prep_kernel<<<32, 256>>>(proj);
    phi_mma_kernel<<<2 * BHC * NSEQ / 128, 512, PHI_SMEMW * 4>>>(q, k);
    chunk_mma_kernel<<<BHC * NCH * 2, 256, CK_SMEMF * sizeof(float)>>>(v);
    prefix_kernel<<<(BHC * MFEAT * EDIM + BHC * MFEAT) / 256, 256>>>();
    out_mma_kernel<<<BHC * NCH, 256, OUT_SMEMF * sizeof(float)>>>(v, out);
}